// round 13
// baseline (speedup 1.0000x reference)
#include <cuda_runtime.h>
#include <cuda_fp16.h>
#include <math.h>
#include <stdint.h>

// Problem constants
#define B_    2
#define S_    2048
#define H_    2048
#define NH_   16
#define NOPE_ 128
#define ROPE_ 64
#define VDIM_ 128
#define RANK_ 512
#define QHD_  192
#define DATT_ 576
#define NTOK_ (B_*S_)

// ---------------- scratch ----------------
__device__ unsigned short g_hs16[(long)NTOK_ * H_];
__device__ unsigned short g_WqT16[(long)(NH_*QHD_) * H_];
__device__ unsigned short g_WkvaT16[(long)DATT_ * H_];
__device__ unsigned short g_WoT16[(long)H_ * (NH_*VDIM_)];
__device__ unsigned short g_Wkvb16[(long)NH_ * 256 * RANK_];
__device__ unsigned short g_q16[(long)NTOK_ * (NH_*QHD_)];       // roped in place
__device__ unsigned short g_ckvraw16[(long)NTOK_ * DATT_];
__device__ unsigned short g_ckv16[(long)NTOK_ * RANK_];          // rms-normed
__device__ unsigned short g_keff16[(long)B_*NH_*S_ * QHD_];      // [ckv@qabs^T | k_pe]
__device__ unsigned short g_veffT16[(long)B_*NH_ * VDIM_ * S_];  // out_absorb @ ckv^T
__device__ unsigned short g_attn16[(long)NTOK_ * (NH_*VDIM_)];

// ---------------- helpers ----------------
__device__ __forceinline__ uint32_t su32(const void* p){ return (uint32_t)__cvta_generic_to_shared((void*)p); }

#define CP_ASYNC16(dst, src) asm volatile("cp.async.cg.shared.global [%0], [%1], 16;" :: "r"(dst), "l"(src))
#define CP_COMMIT()          asm volatile("cp.async.commit_group;" ::: "memory")
#define CP_WAIT(n)           asm volatile("cp.async.wait_group %0;" :: "n"(n) : "memory")

__device__ __forceinline__ void ldmx4(uint32_t& r0, uint32_t& r1, uint32_t& r2, uint32_t& r3, uint32_t addr){
    asm volatile("ldmatrix.sync.aligned.m8n8.x4.shared.b16 {%0,%1,%2,%3}, [%4];"
                 : "=r"(r0), "=r"(r1), "=r"(r2), "=r"(r3) : "r"(addr));
}
__device__ __forceinline__ void mma16816(float* c, const uint32_t* a, const uint32_t* b){
    asm volatile("mma.sync.aligned.m16n8k16.row.col.f32.f16.f16.f32 "
                 "{%0,%1,%2,%3}, {%4,%5,%6,%7}, {%8,%9}, {%0,%1,%2,%3};"
                 : "+f"(c[0]), "+f"(c[1]), "+f"(c[2]), "+f"(c[3])
                 : "r"(a[0]), "r"(a[1]), "r"(a[2]), "r"(a[3]), "r"(b[0]), "r"(b[1]));
}
__device__ __forceinline__ uint32_t packh2(float a, float b){
    __half2 h = __floats2half2_rn(a, b);
    return *reinterpret_cast<uint32_t*>(&h);
}

// ---------------- HMMA NT GEMM: C = A(f16,MxK) @ B(f16,NxK)^T ----------------
// CTA tile 128 x BN, K-tile 64, 256 threads (8 warps = 4M x 2N), 3-stage cp.async.
#define KT_   64
#define PAD_  72

template<int BN, typename CT>
__global__ __launch_bounds__(256, 2)
void hgemm_mma(const __half* __restrict__ A, const __half* __restrict__ B, CT* __restrict__ C,
               int K, int lda, int ldb, int ldc,
               int zdiv, long aOut, long aIn, long bOut, long bIn, long cOut, long cIn)
{
    constexpr int NT = BN / 16;
    constexpr int ASTR = 128 * PAD_ * 2;
    constexpr int BSTR = BN * PAD_ * 2;
    extern __shared__ char smem[];
    const uint32_t saBase = su32(smem);
    const uint32_t sbBase = saBase + 3 * ASTR;

    const int bm = blockIdx.y * 128;
    const int bn = blockIdx.x * BN;

    const int z = blockIdx.z;
    A += (long)(z / zdiv) * aOut + (long)(z % zdiv) * aIn;
    B += (long)(z / zdiv) * bOut + (long)(z % zdiv) * bIn;
    C += (long)(z / zdiv) * cOut + (long)(z % zdiv) * cIn;

    const int NC = K / KT_;

    const int tid = threadIdx.x;
    const int lane = tid & 31, wp = tid >> 5;
    const int mw = wp >> 1;
    const int nw = wp & 1;
    constexpr int WN = BN / 2;

    const int arow = mw * 32 + (lane & 15);
    const int acol = (lane >> 4) * 8;
    const int brow = nw * WN + (lane & 7) + ((lane >> 4) << 3);
    const int bcol = ((lane >> 3) & 1) * 8;

    auto load_async = [&](int kt, int s){
        uint32_t sa = saBase + s * ASTR;
#pragma unroll
        for (int i = 0; i < 4; i++) {
            int v = tid + i * 256;
            int r = v >> 3, c8 = (v & 7) * 8;
            CP_ASYNC16(sa + (r * PAD_ + c8) * 2, A + (long)(bm + r) * lda + kt + c8);
        }
        uint32_t sb = sbBase + s * BSTR;
#pragma unroll
        for (int i = 0; i < BN / 32; i++) {
            int v = tid + i * 256;
            int r = v >> 3, c8 = (v & 7) * 8;
            CP_ASYNC16(sb + (r * PAD_ + c8) * 2, B + (long)(bn + r) * ldb + kt + c8);
        }
    };

    float acc[2][NT][4];
#pragma unroll
    for (int mt = 0; mt < 2; mt++)
#pragma unroll
        for (int nt = 0; nt < NT; nt++)
#pragma unroll
            for (int i = 0; i < 4; i++) acc[mt][nt][i] = 0.f;

    load_async(0, 0);  CP_COMMIT();
    if (NC > 1) load_async(KT_, 1);
    CP_COMMIT();

    for (int c = 0; c < NC; c++) {
        if (c == NC - 1) { CP_WAIT(0); } else { CP_WAIT(1); }
        __syncthreads();
        if (c + 2 < NC) { load_async((c + 2) * KT_, (c + 2) % 3); CP_COMMIT(); }

        const int s = c - (c / 3) * 3;
        const uint32_t sa = saBase + s * ASTR;
        const uint32_t sb = sbBase + s * BSTR;

#pragma unroll
        for (int kk = 0; kk < KT_; kk += 16) {
            uint32_t afr[2][4];
#pragma unroll
            for (int mt = 0; mt < 2; mt++)
                ldmx4(afr[mt][0], afr[mt][1], afr[mt][2], afr[mt][3],
                      sa + (uint32_t)(((arow + mt * 16) * PAD_ + kk + acol) * 2));
            uint32_t bfr[NT][2];
#pragma unroll
            for (int p = 0; p < NT / 2; p++)
                ldmx4(bfr[2*p][0], bfr[2*p][1], bfr[2*p+1][0], bfr[2*p+1][1],
                      sb + (uint32_t)(((brow + p * 16) * PAD_ + kk + bcol) * 2));
#pragma unroll
            for (int mt = 0; mt < 2; mt++)
#pragma unroll
                for (int nt = 0; nt < NT; nt++)
                    mma16816(acc[mt][nt], afr[mt], bfr[nt]);
        }
    }

    const int g = lane >> 2, tg = lane & 3;
#pragma unroll
    for (int mt = 0; mt < 2; mt++) {
        const int row = bm + mw * 32 + mt * 16 + g;
#pragma unroll
        for (int nt = 0; nt < NT; nt++) {
            const int col = bn + nw * WN + nt * 8 + tg * 2;
            if constexpr (sizeof(CT) == 2) {
                *reinterpret_cast<__half2*>((__half*)C + (long)row * ldc + col) =
                    __floats2half2_rn(acc[mt][nt][0], acc[mt][nt][1]);
                *reinterpret_cast<__half2*>((__half*)C + (long)(row + 8) * ldc + col) =
                    __floats2half2_rn(acc[mt][nt][2], acc[mt][nt][3]);
            } else {
                *reinterpret_cast<float2*>((float*)C + (long)row * ldc + col) =
                    make_float2(acc[mt][nt][0], acc[mt][nt][1]);
                *reinterpret_cast<float2*>((float*)C + (long)(row + 8) * ldc + col) =
                    make_float2(acc[mt][nt][2], acc[mt][nt][3]);
            }
        }
    }
}

// ---------------- fused flash attention: scores + softmax + PV ----------------
// iblk = iblk0 - blockIdx.x (heavy-first within each launch half)
#define FBLK  128
#define NBLK  (S_/FBLK)   // 16
#define PADQ  200
#define PADV  136

__global__ __launch_bounds__(256, 1)
void flash_kernel(const __half* __restrict__ q, const __half* __restrict__ keff,
                  const __half* __restrict__ veff, __half* __restrict__ attn, int iblk0)
{
    extern __shared__ char smem[];
    const uint32_t sQa = su32(smem);
    const uint32_t sKa[2] = { sQa + 128*PADQ*2, sQa + 2*128*PADQ*2 };
    const uint32_t sVa[2] = { sQa + 3*128*PADQ*2, sQa + 3*128*PADQ*2 + 128*PADV*2 };

    const int z = blockIdx.z;                  // bh
    const int b = z >> 4, h = z & (NH_-1);
    const int iblk = iblk0 - (int)blockIdx.x;

    const int tid = threadIdx.x, lane = tid & 31, w = tid >> 5;
    const int g = lane >> 2, tg = lane & 3;
    const int m0r = w * 16;

    const __half* Qbase = q + (long)(b*S_ + iblk*FBLK) * (NH_*QHD_) + h*QHD_;
    const __half* Kbase = keff + (long)z * S_ * QHD_;
    const __half* Vbase = veff + (long)z * VDIM_ * S_;

    for (int v = tid; v < 128*24; v += 256) {
        int r = v / 24, c = v % 24;
        CP_ASYNC16(sQa + (r*PADQ + c*8)*2, Qbase + (long)r*(NH_*QHD_) + c*8);
    }
    auto loadK = [&](int j, int s){
        const __half* kb = Kbase + (long)j*FBLK*QHD_;
        for (int v = tid; v < 128*24; v += 256) {
            int r = v / 24, c = v % 24;
            CP_ASYNC16(sKa[s] + (r*PADQ + c*8)*2, kb + (long)r*QHD_ + c*8);
        }
    };
    auto loadV = [&](int j, int s){
        const __half* vb = Vbase + j*FBLK;
        for (int v = tid; v < 128*16; v += 256) {
            int r = v >> 4, c = v & 15;
            CP_ASYNC16(sVa[s] + (r*PADV + c*8)*2, vb + (long)r*S_ + c*8);
        }
    };
    loadK(0, 0); loadV(0, 0); CP_COMMIT();

    float Oacc[16][4];
#pragma unroll
    for (int nt = 0; nt < 16; nt++)
#pragma unroll
        for (int i = 0; i < 4; i++) Oacc[nt][i] = 0.f;
    float m0 = -1e30f, m1 = -1e30f, l0 = 0.f, l1 = 0.f;
    const float scale = 0.07216878364870322f;   // 192^-0.5

    const int arow = lane & 15;
    const int acol = (lane >> 4) * 8;
    const int brow = (lane & 7) + ((lane >> 4) << 3);
    const int bcol = ((lane >> 3) & 1) * 8;

    for (int j = 0; j <= iblk; j++) {
        const int s = j & 1;
        if (j < iblk) { loadK(j+1, s^1); loadV(j+1, s^1); CP_COMMIT(); CP_WAIT(1); }
        else          { CP_WAIT(0); }
        __syncthreads();

        // ---- S = Q @ Keff_j^T ----
        float Sacc[16][4];
#pragma unroll
        for (int nt = 0; nt < 16; nt++)
#pragma unroll
            for (int i = 0; i < 4; i++) Sacc[nt][i] = 0.f;

#pragma unroll
        for (int kk = 0; kk < QHD_; kk += 16) {
            uint32_t afr[4];
            ldmx4(afr[0], afr[1], afr[2], afr[3],
                  sQa + (uint32_t)(((m0r + arow)*PADQ + kk + acol)*2));
            uint32_t bfr[16][2];
#pragma unroll
            for (int p = 0; p < 8; p++)
                ldmx4(bfr[2*p][0], bfr[2*p][1], bfr[2*p+1][0], bfr[2*p+1][1],
                      sKa[s] + (uint32_t)(((p*16 + brow)*PADQ + kk + bcol)*2));
#pragma unroll
            for (int nt = 0; nt < 16; nt++)
                mma16816(Sacc[nt], afr, bfr[nt]);
        }

        // ---- causal mask on diagonal block ----
        if (j == iblk) {
            const int r0 = m0r + g, r1 = r0 + 8;
#pragma unroll
            for (int nt = 0; nt < 16; nt++) {
                const int c0 = nt*8 + tg*2;
                if (c0     > r0) Sacc[nt][0] = -1e30f;
                if (c0 + 1 > r0) Sacc[nt][1] = -1e30f;
                if (c0     > r1) Sacc[nt][2] = -1e30f;
                if (c0 + 1 > r1) Sacc[nt][3] = -1e30f;
            }
        }

        // ---- online softmax ----
        float bm0 = -1e30f, bm1 = -1e30f;
#pragma unroll
        for (int nt = 0; nt < 16; nt++) {
            bm0 = fmaxf(bm0, fmaxf(Sacc[nt][0], Sacc[nt][1]));
            bm1 = fmaxf(bm1, fmaxf(Sacc[nt][2], Sacc[nt][3]));
        }
        bm0 = fmaxf(bm0, __shfl_xor_sync(0xffffffffu, bm0, 1));
        bm0 = fmaxf(bm0, __shfl_xor_sync(0xffffffffu, bm0, 2));
        bm1 = fmaxf(bm1, __shfl_xor_sync(0xffffffffu, bm1, 1));
        bm1 = fmaxf(bm1, __shfl_xor_sync(0xffffffffu, bm1, 2));
        const float mn0 = fmaxf(m0, bm0), mn1 = fmaxf(m1, bm1);
        const float corr0 = __expf((m0 - mn0) * scale);
        const float corr1 = __expf((m1 - mn1) * scale);
        m0 = mn0; m1 = mn1;
        l0 *= corr0; l1 *= corr1;
#pragma unroll
        for (int nt = 0; nt < 16; nt++) {
            Oacc[nt][0] *= corr0; Oacc[nt][1] *= corr0;
            Oacc[nt][2] *= corr1; Oacc[nt][3] *= corr1;
        }

        // ---- P = exp((S-m)*scale); O += P @ Veff_j ----
#pragma unroll
        for (int t = 0; t < 8; t++) {
            const float e00 = __expf((Sacc[2*t  ][0] - m0) * scale);
            const float e01 = __expf((Sacc[2*t  ][1] - m0) * scale);
            const float e02 = __expf((Sacc[2*t  ][2] - m1) * scale);
            const float e03 = __expf((Sacc[2*t  ][3] - m1) * scale);
            const float e10 = __expf((Sacc[2*t+1][0] - m0) * scale);
            const float e11 = __expf((Sacc[2*t+1][1] - m0) * scale);
            const float e12 = __expf((Sacc[2*t+1][2] - m1) * scale);
            const float e13 = __expf((Sacc[2*t+1][3] - m1) * scale);
            l0 += e00 + e01 + e10 + e11;
            l1 += e02 + e03 + e12 + e13;
            uint32_t pa[4];
            pa[0] = packh2(e00, e01);
            pa[1] = packh2(e02, e03);
            pa[2] = packh2(e10, e11);
            pa[3] = packh2(e12, e13);
            uint32_t bfr[16][2];
#pragma unroll
            for (int p = 0; p < 8; p++)
                ldmx4(bfr[2*p][0], bfr[2*p][1], bfr[2*p+1][0], bfr[2*p+1][1],
                      sVa[s] + (uint32_t)(((p*16 + brow)*PADV + t*16 + bcol)*2));
#pragma unroll
            for (int nt = 0; nt < 16; nt++)
                mma16816(Oacc[nt], pa, bfr[nt]);
        }
        __syncthreads();
    }

    // ---- finalize ----
    l0 += __shfl_xor_sync(0xffffffffu, l0, 1);
    l0 += __shfl_xor_sync(0xffffffffu, l0, 2);
    l1 += __shfl_xor_sync(0xffffffffu, l1, 1);
    l1 += __shfl_xor_sync(0xffffffffu, l1, 2);
    const float inv0 = 1.0f / l0, inv1 = 1.0f / l1;

    const long s0 = (long)(b*S_ + iblk*FBLK + m0r + g);
    __half* o0 = attn + (s0 * NH_ + h) * VDIM_;
    __half* o1 = attn + ((s0 + 8) * NH_ + h) * VDIM_;
#pragma unroll
    for (int nt = 0; nt < 16; nt++) {
        const int col = nt*8 + tg*2;
        *reinterpret_cast<__half2*>(o0 + col) = __floats2half2_rn(Oacc[nt][0]*inv0, Oacc[nt][1]*inv0);
        *reinterpret_cast<__half2*>(o1 + col) = __floats2half2_rn(Oacc[nt][2]*inv1, Oacc[nt][3]*inv1);
    }
}

// ---------------- converts ----------------
__global__ __launch_bounds__(256) void f32tof16(const float* __restrict__ in, __half* __restrict__ out, long n4)
{
    long i = blockIdx.x * 256L + threadIdx.x;
    long stride = (long)gridDim.x * 256;
    for (; i < n4; i += stride) {
        float4 v = reinterpret_cast<const float4*>(in)[i];
        reinterpret_cast<__half2*>(out)[2*i]   = __floats2half2_rn(v.x, v.y);
        reinterpret_cast<__half2*>(out)[2*i+1] = __floats2half2_rn(v.z, v.w);
    }
}

__global__ __launch_bounds__(256) void transp_f32f16(const float* __restrict__ in, __half* __restrict__ out,
                                                     int ldin, int ldout, long inB, long outB)
{
    __shared__ float t[32][33];
    const int z = blockIdx.z;
    in += (long)z * inB; out += (long)z * outB;
    const int r0 = blockIdx.y * 32, c0 = blockIdx.x * 32;
    const int x = threadIdx.x & 31, y = threadIdx.x >> 5;
#pragma unroll
    for (int i = 0; i < 32; i += 8)
        t[y + i][x] = in[(long)(r0 + y + i) * ldin + c0 + x];
    __syncthreads();
#pragma unroll
    for (int i = 0; i < 32; i += 8)
        out[(long)(c0 + y + i) * ldout + r0 + x] = __float2half_rn(t[x][y + i]);
}

// ---------------- rmsnorm + rope ----------------
__global__ __launch_bounds__(128)
void rmsrope_kernel(__half* __restrict__ q16, const __half* __restrict__ ckvraw,
                    const int* __restrict__ pos_ids, const float* __restrict__ cosc,
                    const float* __restrict__ sinc, const float* __restrict__ lnw,
                    __half* __restrict__ ckv16, __half* __restrict__ keff)
{
    const int t = blockIdx.x;
    const int b = t / S_, s = t - b * S_;
    const __half* cv = ckvraw + (long)t * DATT_;

    __shared__ float red[4];
    float ss = 0.f;
    for (int i = threadIdx.x; i < RANK_; i += 128) { float v = __half2float(cv[i]); ss += v * v; }
#pragma unroll
    for (int o = 16; o; o >>= 1) ss += __shfl_xor_sync(0xffffffffu, ss, o);
    if ((threadIdx.x & 31) == 0) red[threadIdx.x >> 5] = ss;
    __syncthreads();
    const float inv = rsqrtf((red[0] + red[1] + red[2] + red[3]) * (1.0f / RANK_) + 1e-6f);

    __half* kd = ckv16 + (long)t * RANK_;
    for (int i = threadIdx.x; i < RANK_; i += 128)
        kd[i] = __float2half_rn(__half2float(cv[i]) * inv * lnw[i]);

    const int pos = pos_ids[t];
    const float* cr = cosc + (long)pos * ROPE_;
    const float* sr = sinc + (long)pos * ROPE_;

    if (threadIdx.x < 32) {
        const int j = threadIdx.x;
        const float c = cr[j], sn = sr[j];
        const float e = __half2float(cv[RANK_ + 2*j]), o = __half2float(cv[RANK_ + 2*j + 1]);
        const __half r0 = __float2half_rn(e * c - o * sn);
        const __half r1 = __float2half_rn(o * c + e * sn);
#pragma unroll
        for (int h = 0; h < NH_; h++) {
            __half* kb = keff + ((long)(b * NH_ + h) * S_ + s) * QHD_ + NOPE_;
            kb[j] = r0; kb[32 + j] = r1;
        }
    }

    for (int p = threadIdx.x; p < NH_ * 32; p += 128) {
        const int h = p >> 5, j = p & 31;
        const float c = cr[j], sn = sr[j];
        __half* qs = q16 + (long)t * (NH_*QHD_) + h * QHD_ + NOPE_;
        const float e = __half2float(qs[2*j]), o = __half2float(qs[2*j + 1]);
        __syncwarp();
        qs[j]      = __float2half_rn(e * c - o * sn);
        qs[32 + j] = __float2half_rn(o * c + e * sn);
    }
}

// ---------------- host ----------------
template<typename CT>
static void hgemm_t(const __half* A, const __half* B, CT* C,
                    int M, int N, int K, int lda, int ldb, int ldc, int Z, int zdiv,
                    long aO, long aI, long bO, long bI, long cO, long cI,
                    cudaStream_t st)
{
    if (N % 128 == 0) {
        int sm = 3 * (128 + 128) * PAD_ * 2;
        cudaFuncSetAttribute(hgemm_mma<128, CT>, cudaFuncAttributeMaxDynamicSharedMemorySize, sm);
        dim3 g(N / 128, M / 128, Z);
        hgemm_mma<128, CT><<<g, 256, sm, st>>>(A, B, C, K, lda, ldb, ldc, zdiv, aO, aI, bO, bI, cO, cI);
    } else {
        int sm = 3 * (128 + 64) * PAD_ * 2;
        cudaFuncSetAttribute(hgemm_mma<64, CT>, cudaFuncAttributeMaxDynamicSharedMemorySize, sm);
        dim3 g(N / 64, M / 128, Z);
        hgemm_mma<64, CT><<<g, 256, sm, st>>>(A, B, C, K, lda, ldb, ldc, zdiv, aO, aI, bO, bI, cO, cI);
    }
}

static void cvt(const float* in, __half* out, long n, cudaStream_t st)
{
    long n4 = n / 4;
    int blocks = (int)((n4 + 255) / 256); if (blocks > 8192) blocks = 8192;
    f32tof16<<<blocks, 256, 0, st>>>(in, out, n4);
}

extern "C" void kernel_launch(void* const* d_in, const int* in_sizes, int n_in,
                              void* d_out, int out_size)
{
    const float* hs    = (const float*)d_in[0];
    const int*   pos   = (const int*)d_in[2];
    const float* cosc  = (const float*)d_in[3];
    const float* sinc  = (const float*)d_in[4];
    const float* Wq    = (const float*)d_in[5];
    const float* Wkv_a = (const float*)d_in[6];
    const float* lnw   = (const float*)d_in[7];
    const float* Wkv_b = (const float*)d_in[8];
    const float* Wo    = (const float*)d_in[9];
    float* out = (float*)d_out;

    __half *hs16, *WqT, *WkvaT, *WoT, *Wkvb16, *q16, *ckvraw16, *ckv16, *keff16, *veffT, *attn16;
    cudaGetSymbolAddress((void**)&hs16, g_hs16);
    cudaGetSymbolAddress((void**)&WqT, g_WqT16);
    cudaGetSymbolAddress((void**)&WkvaT, g_WkvaT16);
    cudaGetSymbolAddress((void**)&WoT, g_WoT16);
    cudaGetSymbolAddress((void**)&Wkvb16, g_Wkvb16);
    cudaGetSymbolAddress((void**)&q16, g_q16);
    cudaGetSymbolAddress((void**)&ckvraw16, g_ckvraw16);
    cudaGetSymbolAddress((void**)&ckv16, g_ckv16);
    cudaGetSymbolAddress((void**)&keff16, g_keff16);
    cudaGetSymbolAddress((void**)&veffT, g_veffT16);
    cudaGetSymbolAddress((void**)&attn16, g_attn16);

    // Side stream + events for captured fork-join (legal fork: s2 waits evA first).
    cudaStream_t s2;
    cudaStreamCreateWithFlags(&s2, cudaStreamNonBlocking);
    cudaEvent_t evA, evB, evC, evD, evE, evF, evG;
    cudaEventCreateWithFlags(&evA, cudaEventDisableTiming);
    cudaEventCreateWithFlags(&evB, cudaEventDisableTiming);
    cudaEventCreateWithFlags(&evC, cudaEventDisableTiming);
    cudaEventCreateWithFlags(&evD, cudaEventDisableTiming);
    cudaEventCreateWithFlags(&evE, cudaEventDisableTiming);
    cudaEventCreateWithFlags(&evF, cudaEventDisableTiming);
    cudaEventCreateWithFlags(&evG, cudaEventDisableTiming);
    cudaStream_t s0 = 0;

    // ---- s0: hs convert, then fork ----
    cvt(hs, hs16, (long)NTOK_ * H_, s0);
    cudaEventRecord(evA, s0);

    // ---- s2 (forked on evA): kv-side prep + ckv projection, then WoT ----
    cudaStreamWaitEvent(s2, evA, 0);
    transp_f32f16<<<dim3(DATT_/32, H_/32, 1), 256, 0, s2>>>(Wkv_a, WkvaT, DATT_, H_, 0, 0);
    cvt(Wkv_b, Wkvb16, (long)NH_ * 256 * RANK_, s2);
    hgemm_t<__half>(hs16, WkvaT, ckvraw16, NTOK_, DATT_, H_, H_, H_, DATT_, 1, 1,
                    0,0,0,0,0,0, s2);
    cudaEventRecord(evB, s2);                       // ckvraw16 + Wkvb16 ready
    transp_f32f16<<<dim3(H_/32, H_/32, 1), 256, 0, s2>>>(Wo, WoT, H_, H_, 0, 0);
    cudaEventRecord(evE, s2);                       // WoT ready

    // ---- s0: WqT + q projection (overlaps s2 prep) ----
    transp_f32f16<<<dim3((NH_*QHD_)/32, H_/32, 1), 256, 0, s0>>>(Wq, WqT, NH_*QHD_, H_, 0, 0);
    hgemm_t<__half>(hs16, WqT, q16, NTOK_, NH_*QHD_, H_, H_, H_, NH_*QHD_, 1, 1,
                    0,0,0,0,0,0, s0);

    // ---- join: rmsrope needs q16 (s0) + ckvraw16 (s2) ----
    cudaStreamWaitEvent(s0, evB, 0);
    rmsrope_kernel<<<NTOK_, 128, 0, s0>>>(q16, ckvraw16, pos, cosc, sinc, lnw, ckv16, keff16);
    cudaEventRecord(evC, s0);

    // ---- fork: keff on s0, veff on s2 ----
    hgemm_t<__half>(ckv16, Wkvb16, keff16, S_, NOPE_, RANK_, RANK_, RANK_, QHD_,
          B_*NH_, NH_,
          (long)S_*RANK_, 0,
          0, (long)256*RANK_,
          (long)NH_*S_*QHD_, (long)S_*QHD_, s0);

    cudaStreamWaitEvent(s2, evC, 0);
    hgemm_t<__half>(Wkvb16 + (long)NOPE_*RANK_, ckv16, veffT, VDIM_, S_, RANK_,
          RANK_, RANK_, S_,
          B_*NH_, NH_,
          0, (long)256*RANK_,
          (long)S_*RANK_, 0,
          (long)NH_*VDIM_*S_, (long)VDIM_*S_, s2);
    cudaEventRecord(evD, s2);
    cudaStreamWaitEvent(s0, evD, 0);

    // ---- flash attention split: heavy half (iblk 15..8) then light half ----
    int fsm = (3*128*PADQ + 2*128*PADV) * 2;   // 223232 bytes
    cudaFuncSetAttribute(flash_kernel, cudaFuncAttributeMaxDynamicSharedMemorySize, fsm);

    flash_kernel<<<dim3(8, 1, B_*NH_), 256, fsm, s0>>>(q16, keff16, veffT, attn16, NBLK - 1); // iblk 15..8
    cudaEventRecord(evF, s0);                       // tokens [1024,2048) per batch done

    // ---- s2: Wo on heavy-half rows, overlapping light-half flash ----
    cudaStreamWaitEvent(s2, evE, 0);                // ensure WoT (recorded earlier on s2; in-order anyway)
    cudaStreamWaitEvent(s2, evF, 0);
    hgemm_t<float>(attn16 + (long)(S_/2)*(NH_*VDIM_), WoT, out + (long)(S_/2)*H_,
                   S_/2, H_, NH_*VDIM_, NH_*VDIM_, NH_*VDIM_, H_,
                   B_, 1,
                   (long)S_*(NH_*VDIM_), 0,
                   0, 0,
                   (long)S_*H_, 0, s2);
    cudaEventRecord(evG, s2);

    // ---- s0: light half flash (iblk 7..0), then Wo on its rows ----
    flash_kernel<<<dim3(8, 1, B_*NH_), 256, fsm, s0>>>(q16, keff16, veffT, attn16, NBLK/2 - 1); // iblk 7..0
    cudaStreamWaitEvent(s0, evE, 0);
    hgemm_t<float>(attn16, WoT, out,
                   S_/2, H_, NH_*VDIM_, NH_*VDIM_, NH_*VDIM_, H_,
                   B_, 1,
                   (long)S_*(NH_*VDIM_), 0,
                   0, 0,
                   (long)S_*H_, 0, s0);

    // ---- join s2 back before capture end ----
    cudaStreamWaitEvent(s0, evG, 0);
}

// round 14
// speedup vs baseline: 1.0304x; 1.0304x over previous
#include <cuda_runtime.h>
#include <cuda_fp16.h>
#include <math.h>
#include <stdint.h>

// Problem constants
#define B_    2
#define S_    2048
#define H_    2048
#define NH_   16
#define NOPE_ 128
#define ROPE_ 64
#define VDIM_ 128
#define RANK_ 512
#define QHD_  192
#define DATT_ 576
#define NTOK_ (B_*S_)

// ---------------- scratch ----------------
__device__ unsigned short g_hs16[(long)NTOK_ * H_];
__device__ unsigned short g_WqT16[(long)(NH_*QHD_) * H_];
__device__ unsigned short g_WkvaT16[(long)DATT_ * H_];
__device__ unsigned short g_WoT16[(long)H_ * (NH_*VDIM_)];
__device__ unsigned short g_Wkvb16[(long)NH_ * 256 * RANK_];
__device__ unsigned short g_q16[(long)NTOK_ * (NH_*QHD_)];       // roped in place
__device__ unsigned short g_ckvraw16[(long)NTOK_ * DATT_];
__device__ unsigned short g_ckv16[(long)NTOK_ * RANK_];          // rms-normed
__device__ unsigned short g_keff16[(long)B_*NH_*S_ * QHD_];      // [ckv@qabs^T | k_pe]
__device__ unsigned short g_veffT16[(long)B_*NH_ * VDIM_ * S_];  // out_absorb @ ckv^T
__device__ unsigned short g_attn16[(long)NTOK_ * (NH_*VDIM_)];

// ---------------- helpers ----------------
__device__ __forceinline__ uint32_t su32(const void* p){ return (uint32_t)__cvta_generic_to_shared((void*)p); }

#define CP_ASYNC16(dst, src) asm volatile("cp.async.cg.shared.global [%0], [%1], 16;" :: "r"(dst), "l"(src))
#define CP_COMMIT()          asm volatile("cp.async.commit_group;" ::: "memory")
#define CP_WAIT(n)           asm volatile("cp.async.wait_group %0;" :: "n"(n) : "memory")

__device__ __forceinline__ void ldmx4(uint32_t& r0, uint32_t& r1, uint32_t& r2, uint32_t& r3, uint32_t addr){
    asm volatile("ldmatrix.sync.aligned.m8n8.x4.shared.b16 {%0,%1,%2,%3}, [%4];"
                 : "=r"(r0), "=r"(r1), "=r"(r2), "=r"(r3) : "r"(addr));
}
__device__ __forceinline__ void mma16816(float* c, const uint32_t* a, const uint32_t* b){
    asm volatile("mma.sync.aligned.m16n8k16.row.col.f32.f16.f16.f32 "
                 "{%0,%1,%2,%3}, {%4,%5,%6,%7}, {%8,%9}, {%0,%1,%2,%3};"
                 : "+f"(c[0]), "+f"(c[1]), "+f"(c[2]), "+f"(c[3])
                 : "r"(a[0]), "r"(a[1]), "r"(a[2]), "r"(a[3]), "r"(b[0]), "r"(b[1]));
}
__device__ __forceinline__ uint32_t packh2(float a, float b){
    __half2 h = __floats2half2_rn(a, b);
    return *reinterpret_cast<uint32_t*>(&h);
}

// ---------------- HMMA NT GEMM: C = A(f16,MxK) @ B(f16,NxK)^T ----------------
// CTA tile 128 x BN, K-tile 64, 256 threads (8 warps = 4M x 2N), 3-stage cp.async.
#define KT_   64
#define PAD_  72

template<int BN, typename CT>
__global__ __launch_bounds__(256, 2)
void hgemm_mma(const __half* __restrict__ A, const __half* __restrict__ B, CT* __restrict__ C,
               int K, int lda, int ldb, int ldc,
               int zdiv, long aOut, long aIn, long bOut, long bIn, long cOut, long cIn)
{
    constexpr int NT = BN / 16;
    constexpr int ASTR = 128 * PAD_ * 2;
    constexpr int BSTR = BN * PAD_ * 2;
    extern __shared__ char smem[];
    const uint32_t saBase = su32(smem);
    const uint32_t sbBase = saBase + 3 * ASTR;

    const int bm = blockIdx.y * 128;
    const int bn = blockIdx.x * BN;

    const int z = blockIdx.z;
    A += (long)(z / zdiv) * aOut + (long)(z % zdiv) * aIn;
    B += (long)(z / zdiv) * bOut + (long)(z % zdiv) * bIn;
    C += (long)(z / zdiv) * cOut + (long)(z % zdiv) * cIn;

    const int NC = K / KT_;

    const int tid = threadIdx.x;
    const int lane = tid & 31, wp = tid >> 5;
    const int mw = wp >> 1;
    const int nw = wp & 1;
    constexpr int WN = BN / 2;

    const int arow = mw * 32 + (lane & 15);
    const int acol = (lane >> 4) * 8;
    const int brow = nw * WN + (lane & 7) + ((lane >> 4) << 3);
    const int bcol = ((lane >> 3) & 1) * 8;

    auto load_async = [&](int kt, int s){
        uint32_t sa = saBase + s * ASTR;
#pragma unroll
        for (int i = 0; i < 4; i++) {
            int v = tid + i * 256;
            int r = v >> 3, c8 = (v & 7) * 8;
            CP_ASYNC16(sa + (r * PAD_ + c8) * 2, A + (long)(bm + r) * lda + kt + c8);
        }
        uint32_t sb = sbBase + s * BSTR;
#pragma unroll
        for (int i = 0; i < BN / 32; i++) {
            int v = tid + i * 256;
            int r = v >> 3, c8 = (v & 7) * 8;
            CP_ASYNC16(sb + (r * PAD_ + c8) * 2, B + (long)(bn + r) * ldb + kt + c8);
        }
    };

    float acc[2][NT][4];
#pragma unroll
    for (int mt = 0; mt < 2; mt++)
#pragma unroll
        for (int nt = 0; nt < NT; nt++)
#pragma unroll
            for (int i = 0; i < 4; i++) acc[mt][nt][i] = 0.f;

    load_async(0, 0);  CP_COMMIT();
    if (NC > 1) load_async(KT_, 1);
    CP_COMMIT();

    for (int c = 0; c < NC; c++) {
        if (c == NC - 1) { CP_WAIT(0); } else { CP_WAIT(1); }
        __syncthreads();
        if (c + 2 < NC) { load_async((c + 2) * KT_, (c + 2) % 3); CP_COMMIT(); }

        const int s = c - (c / 3) * 3;
        const uint32_t sa = saBase + s * ASTR;
        const uint32_t sb = sbBase + s * BSTR;

#pragma unroll
        for (int kk = 0; kk < KT_; kk += 16) {
            uint32_t afr[2][4];
#pragma unroll
            for (int mt = 0; mt < 2; mt++)
                ldmx4(afr[mt][0], afr[mt][1], afr[mt][2], afr[mt][3],
                      sa + (uint32_t)(((arow + mt * 16) * PAD_ + kk + acol) * 2));
            uint32_t bfr[NT][2];
#pragma unroll
            for (int p = 0; p < NT / 2; p++)
                ldmx4(bfr[2*p][0], bfr[2*p][1], bfr[2*p+1][0], bfr[2*p+1][1],
                      sb + (uint32_t)(((brow + p * 16) * PAD_ + kk + bcol) * 2));
#pragma unroll
            for (int mt = 0; mt < 2; mt++)
#pragma unroll
                for (int nt = 0; nt < NT; nt++)
                    mma16816(acc[mt][nt], afr[mt], bfr[nt]);
        }
    }

    const int g = lane >> 2, tg = lane & 3;
#pragma unroll
    for (int mt = 0; mt < 2; mt++) {
        const int row = bm + mw * 32 + mt * 16 + g;
#pragma unroll
        for (int nt = 0; nt < NT; nt++) {
            const int col = bn + nw * WN + nt * 8 + tg * 2;
            if constexpr (sizeof(CT) == 2) {
                *reinterpret_cast<__half2*>((__half*)C + (long)row * ldc + col) =
                    __floats2half2_rn(acc[mt][nt][0], acc[mt][nt][1]);
                *reinterpret_cast<__half2*>((__half*)C + (long)(row + 8) * ldc + col) =
                    __floats2half2_rn(acc[mt][nt][2], acc[mt][nt][3]);
            } else {
                *reinterpret_cast<float2*>((float*)C + (long)row * ldc + col) =
                    make_float2(acc[mt][nt][0], acc[mt][nt][1]);
                *reinterpret_cast<float2*>((float*)C + (long)(row + 8) * ldc + col) =
                    make_float2(acc[mt][nt][2], acc[mt][nt][3]);
            }
        }
    }
}

// ---------------- fused flash attention: scores + softmax + PV ----------------
// Single __syncthreads per j-iteration: wait -> barrier -> prefetch j+1 -> compute.
#define FBLK  128
#define NBLK  (S_/FBLK)   // 16
#define PADQ  200
#define PADV  136

__global__ __launch_bounds__(256, 1)
void flash_kernel(const __half* __restrict__ q, const __half* __restrict__ keff,
                  const __half* __restrict__ veff, __half* __restrict__ attn)
{
    extern __shared__ char smem[];
    const uint32_t sQa = su32(smem);
    const uint32_t sKa[2] = { sQa + 128*PADQ*2, sQa + 2*128*PADQ*2 };
    const uint32_t sVa[2] = { sQa + 3*128*PADQ*2, sQa + 3*128*PADQ*2 + 128*PADV*2 };

    const int z = blockIdx.z;                  // bh
    const int b = z >> 4, h = z & (NH_-1);
    const int iblk = (NBLK - 1) - blockIdx.x;  // heavy blocks first

    const int tid = threadIdx.x, lane = tid & 31, w = tid >> 5;
    const int g = lane >> 2, tg = lane & 3;
    const int m0r = w * 16;

    const __half* Qbase = q + (long)(b*S_ + iblk*FBLK) * (NH_*QHD_) + h*QHD_;
    const __half* Kbase = keff + (long)z * S_ * QHD_;
    const __half* Vbase = veff + (long)z * VDIM_ * S_;

    for (int v = tid; v < 128*24; v += 256) {
        int r = v / 24, c = v % 24;
        CP_ASYNC16(sQa + (r*PADQ + c*8)*2, Qbase + (long)r*(NH_*QHD_) + c*8);
    }
    auto loadK = [&](int j, int s){
        const __half* kb = Kbase + (long)j*FBLK*QHD_;
        for (int v = tid; v < 128*24; v += 256) {
            int r = v / 24, c = v % 24;
            CP_ASYNC16(sKa[s] + (r*PADQ + c*8)*2, kb + (long)r*QHD_ + c*8);
        }
    };
    auto loadV = [&](int j, int s){
        const __half* vb = Vbase + j*FBLK;
        for (int v = tid; v < 128*16; v += 256) {
            int r = v >> 4, c = v & 15;
            CP_ASYNC16(sVa[s] + (r*PADV + c*8)*2, vb + (long)r*S_ + c*8);
        }
    };
    loadK(0, 0); loadV(0, 0); CP_COMMIT();

    float Oacc[16][4];
#pragma unroll
    for (int nt = 0; nt < 16; nt++)
#pragma unroll
        for (int i = 0; i < 4; i++) Oacc[nt][i] = 0.f;
    float m0 = -1e30f, m1 = -1e30f, l0 = 0.f, l1 = 0.f;
    const float scale = 0.07216878364870322f;   // 192^-0.5

    const int arow = lane & 15;
    const int acol = (lane >> 4) * 8;
    const int brow = (lane & 7) + ((lane >> 4) << 3);
    const int bcol = ((lane >> 3) & 1) * 8;

    for (int j = 0; j <= iblk; j++) {
        const int s = j & 1;
        CP_WAIT(0);            // only one group in flight at this point
        __syncthreads();       // all warps done with buffer s^1 (iter j-1)
        if (j < iblk) { loadK(j+1, s^1); loadV(j+1, s^1); CP_COMMIT(); }

        // ---- S = Q @ Keff_j^T ----
        float Sacc[16][4];
#pragma unroll
        for (int nt = 0; nt < 16; nt++)
#pragma unroll
            for (int i = 0; i < 4; i++) Sacc[nt][i] = 0.f;

#pragma unroll
        for (int kk = 0; kk < QHD_; kk += 16) {
            uint32_t afr[4];
            ldmx4(afr[0], afr[1], afr[2], afr[3],
                  sQa + (uint32_t)(((m0r + arow)*PADQ + kk + acol)*2));
            uint32_t bfr[16][2];
#pragma unroll
            for (int p = 0; p < 8; p++)
                ldmx4(bfr[2*p][0], bfr[2*p][1], bfr[2*p+1][0], bfr[2*p+1][1],
                      sKa[s] + (uint32_t)(((p*16 + brow)*PADQ + kk + bcol)*2));
#pragma unroll
            for (int nt = 0; nt < 16; nt++)
                mma16816(Sacc[nt], afr, bfr[nt]);
        }

        // ---- causal mask on diagonal block ----
        if (j == iblk) {
            const int r0 = m0r + g, r1 = r0 + 8;
#pragma unroll
            for (int nt = 0; nt < 16; nt++) {
                const int c0 = nt*8 + tg*2;
                if (c0     > r0) Sacc[nt][0] = -1e30f;
                if (c0 + 1 > r0) Sacc[nt][1] = -1e30f;
                if (c0     > r1) Sacc[nt][2] = -1e30f;
                if (c0 + 1 > r1) Sacc[nt][3] = -1e30f;
            }
        }

        // ---- online softmax ----
        float bm0 = -1e30f, bm1 = -1e30f;
#pragma unroll
        for (int nt = 0; nt < 16; nt++) {
            bm0 = fmaxf(bm0, fmaxf(Sacc[nt][0], Sacc[nt][1]));
            bm1 = fmaxf(bm1, fmaxf(Sacc[nt][2], Sacc[nt][3]));
        }
        bm0 = fmaxf(bm0, __shfl_xor_sync(0xffffffffu, bm0, 1));
        bm0 = fmaxf(bm0, __shfl_xor_sync(0xffffffffu, bm0, 2));
        bm1 = fmaxf(bm1, __shfl_xor_sync(0xffffffffu, bm1, 1));
        bm1 = fmaxf(bm1, __shfl_xor_sync(0xffffffffu, bm1, 2));
        const float mn0 = fmaxf(m0, bm0), mn1 = fmaxf(m1, bm1);
        const float corr0 = __expf((m0 - mn0) * scale);
        const float corr1 = __expf((m1 - mn1) * scale);
        m0 = mn0; m1 = mn1;
        l0 *= corr0; l1 *= corr1;
#pragma unroll
        for (int nt = 0; nt < 16; nt++) {
            Oacc[nt][0] *= corr0; Oacc[nt][1] *= corr0;
            Oacc[nt][2] *= corr1; Oacc[nt][3] *= corr1;
        }

        // ---- P = exp((S-m)*scale); O += P @ Veff_j ----
#pragma unroll
        for (int t = 0; t < 8; t++) {
            const float e00 = __expf((Sacc[2*t  ][0] - m0) * scale);
            const float e01 = __expf((Sacc[2*t  ][1] - m0) * scale);
            const float e02 = __expf((Sacc[2*t  ][2] - m1) * scale);
            const float e03 = __expf((Sacc[2*t  ][3] - m1) * scale);
            const float e10 = __expf((Sacc[2*t+1][0] - m0) * scale);
            const float e11 = __expf((Sacc[2*t+1][1] - m0) * scale);
            const float e12 = __expf((Sacc[2*t+1][2] - m1) * scale);
            const float e13 = __expf((Sacc[2*t+1][3] - m1) * scale);
            l0 += e00 + e01 + e10 + e11;
            l1 += e02 + e03 + e12 + e13;
            uint32_t pa[4];
            pa[0] = packh2(e00, e01);
            pa[1] = packh2(e02, e03);
            pa[2] = packh2(e10, e11);
            pa[3] = packh2(e12, e13);
            uint32_t bfr[16][2];
#pragma unroll
            for (int p = 0; p < 8; p++)
                ldmx4(bfr[2*p][0], bfr[2*p][1], bfr[2*p+1][0], bfr[2*p+1][1],
                      sVa[s] + (uint32_t)(((p*16 + brow)*PADV + t*16 + bcol)*2));
#pragma unroll
            for (int nt = 0; nt < 16; nt++)
                mma16816(Oacc[nt], pa, bfr[nt]);
        }
    }

    // ---- finalize ----
    l0 += __shfl_xor_sync(0xffffffffu, l0, 1);
    l0 += __shfl_xor_sync(0xffffffffu, l0, 2);
    l1 += __shfl_xor_sync(0xffffffffu, l1, 1);
    l1 += __shfl_xor_sync(0xffffffffu, l1, 2);
    const float inv0 = 1.0f / l0, inv1 = 1.0f / l1;

    const long s0 = (long)(b*S_ + iblk*FBLK + m0r + g);
    __half* o0 = attn + (s0 * NH_ + h) * VDIM_;
    __half* o1 = attn + ((s0 + 8) * NH_ + h) * VDIM_;
#pragma unroll
    for (int nt = 0; nt < 16; nt++) {
        const int col = nt*8 + tg*2;
        *reinterpret_cast<__half2*>(o0 + col) = __floats2half2_rn(Oacc[nt][0]*inv0, Oacc[nt][1]*inv0);
        *reinterpret_cast<__half2*>(o1 + col) = __floats2half2_rn(Oacc[nt][2]*inv1, Oacc[nt][3]*inv1);
    }
}

// ---------------- converts ----------------
__global__ __launch_bounds__(256) void f32tof16(const float* __restrict__ in, __half* __restrict__ out, long n4)
{
    long i = blockIdx.x * 256L + threadIdx.x;
    long stride = (long)gridDim.x * 256;
    for (; i < n4; i += stride) {
        float4 v = reinterpret_cast<const float4*>(in)[i];
        reinterpret_cast<__half2*>(out)[2*i]   = __floats2half2_rn(v.x, v.y);
        reinterpret_cast<__half2*>(out)[2*i+1] = __floats2half2_rn(v.z, v.w);
    }
}

__global__ __launch_bounds__(256) void transp_f32f16(const float* __restrict__ in, __half* __restrict__ out,
                                                     int ldin, int ldout, long inB, long outB)
{
    __shared__ float t[32][33];
    const int z = blockIdx.z;
    in += (long)z * inB; out += (long)z * outB;
    const int r0 = blockIdx.y * 32, c0 = blockIdx.x * 32;
    const int x = threadIdx.x & 31, y = threadIdx.x >> 5;
#pragma unroll
    for (int i = 0; i < 32; i += 8)
        t[y + i][x] = in[(long)(r0 + y + i) * ldin + c0 + x];
    __syncthreads();
#pragma unroll
    for (int i = 0; i < 32; i += 8)
        out[(long)(c0 + y + i) * ldout + r0 + x] = __float2half_rn(t[x][y + i]);
}

// ---------------- rmsnorm + rope ----------------
__global__ __launch_bounds__(128)
void rmsrope_kernel(__half* __restrict__ q16, const __half* __restrict__ ckvraw,
                    const int* __restrict__ pos_ids, const float* __restrict__ cosc,
                    const float* __restrict__ sinc, const float* __restrict__ lnw,
                    __half* __restrict__ ckv16, __half* __restrict__ keff)
{
    const int t = blockIdx.x;
    const int b = t / S_, s = t - b * S_;
    const __half* cv = ckvraw + (long)t * DATT_;

    __shared__ float red[4];
    __shared__ __half kpe[64];
    float ss = 0.f;
    for (int i = threadIdx.x; i < RANK_; i += 128) { float v = __half2float(cv[i]); ss += v * v; }
#pragma unroll
    for (int o = 16; o; o >>= 1) ss += __shfl_xor_sync(0xffffffffu, ss, o);
    if ((threadIdx.x & 31) == 0) red[threadIdx.x >> 5] = ss;
    __syncthreads();
    const float inv = rsqrtf((red[0] + red[1] + red[2] + red[3]) * (1.0f / RANK_) + 1e-6f);

    __half* kd = ckv16 + (long)t * RANK_;
    for (int i = threadIdx.x; i < RANK_; i += 128)
        kd[i] = __float2half_rn(__half2float(cv[i]) * inv * lnw[i]);

    const int pos = pos_ids[t];
    const float* cr = cosc + (long)pos * ROPE_;
    const float* sr = sinc + (long)pos * ROPE_;

    // k_pe rope -> stage in smem, then vectorized replicate into all heads
    if (threadIdx.x < 32) {
        const int j = threadIdx.x;
        const float c = cr[j], sn = sr[j];
        const float e = __half2float(cv[RANK_ + 2*j]), o = __half2float(cv[RANK_ + 2*j + 1]);
        kpe[j]      = __float2half_rn(e * c - o * sn);
        kpe[32 + j] = __float2half_rn(o * c + e * sn);
    }
    __syncthreads();
    {   // 16 heads x 8 uint4 (64 halfs) = 128 threads, one 16B store each
        const int h = threadIdx.x >> 3, c4 = threadIdx.x & 7;
        __half* kb = keff + ((long)(b * NH_ + h) * S_ + s) * QHD_ + NOPE_;
        reinterpret_cast<uint4*>(kb)[c4] = reinterpret_cast<const uint4*>(kpe)[c4];
    }

    // q_pe rope in place (deinterleave)
    for (int p = threadIdx.x; p < NH_ * 32; p += 128) {
        const int h = p >> 5, j = p & 31;
        const float c = cr[j], sn = sr[j];
        __half* qs = q16 + (long)t * (NH_*QHD_) + h * QHD_ + NOPE_;
        const float e = __half2float(qs[2*j]), o = __half2float(qs[2*j + 1]);
        __syncwarp();
        qs[j]      = __float2half_rn(e * c - o * sn);
        qs[32 + j] = __float2half_rn(o * c + e * sn);
    }
}

// ---------------- host ----------------
template<typename CT>
static void hgemm_t(const __half* A, const __half* B, CT* C,
                    int M, int N, int K, int lda, int ldb, int ldc, int Z, int zdiv,
                    long aO, long aI, long bO, long bI, long cO, long cI,
                    cudaStream_t st)
{
    if (N % 128 == 0) {
        int sm = 3 * (128 + 128) * PAD_ * 2;
        cudaFuncSetAttribute(hgemm_mma<128, CT>, cudaFuncAttributeMaxDynamicSharedMemorySize, sm);
        dim3 g(N / 128, M / 128, Z);
        hgemm_mma<128, CT><<<g, 256, sm, st>>>(A, B, C, K, lda, ldb, ldc, zdiv, aO, aI, bO, bI, cO, cI);
    } else {
        int sm = 3 * (128 + 64) * PAD_ * 2;
        cudaFuncSetAttribute(hgemm_mma<64, CT>, cudaFuncAttributeMaxDynamicSharedMemorySize, sm);
        dim3 g(N / 64, M / 128, Z);
        hgemm_mma<64, CT><<<g, 256, sm, st>>>(A, B, C, K, lda, ldb, ldc, zdiv, aO, aI, bO, bI, cO, cI);
    }
}

static void cvt(const float* in, __half* out, long n, cudaStream_t st)
{
    long n4 = n / 4;
    int blocks = (int)((n4 + 255) / 256); if (blocks > 8192) blocks = 8192;
    f32tof16<<<blocks, 256, 0, st>>>(in, out, n4);
}

extern "C" void kernel_launch(void* const* d_in, const int* in_sizes, int n_in,
                              void* d_out, int out_size)
{
    const float* hs    = (const float*)d_in[0];
    const int*   pos   = (const int*)d_in[2];
    const float* cosc  = (const float*)d_in[3];
    const float* sinc  = (const float*)d_in[4];
    const float* Wq    = (const float*)d_in[5];
    const float* Wkv_a = (const float*)d_in[6];
    const float* lnw   = (const float*)d_in[7];
    const float* Wkv_b = (const float*)d_in[8];
    const float* Wo    = (const float*)d_in[9];
    float* out = (float*)d_out;

    __half *hs16, *WqT, *WkvaT, *WoT, *Wkvb16, *q16, *ckvraw16, *ckv16, *keff16, *veffT, *attn16;
    cudaGetSymbolAddress((void**)&hs16, g_hs16);
    cudaGetSymbolAddress((void**)&WqT, g_WqT16);
    cudaGetSymbolAddress((void**)&WkvaT, g_WkvaT16);
    cudaGetSymbolAddress((void**)&WoT, g_WoT16);
    cudaGetSymbolAddress((void**)&Wkvb16, g_Wkvb16);
    cudaGetSymbolAddress((void**)&q16, g_q16);
    cudaGetSymbolAddress((void**)&ckvraw16, g_ckvraw16);
    cudaGetSymbolAddress((void**)&ckv16, g_ckv16);
    cudaGetSymbolAddress((void**)&keff16, g_keff16);
    cudaGetSymbolAddress((void**)&veffT, g_veffT16);
    cudaGetSymbolAddress((void**)&attn16, g_attn16);

    // R10 DAG exactly (legal fork: s2's first op waits evA).
    cudaStream_t s2;
    cudaStreamCreateWithFlags(&s2, cudaStreamNonBlocking);
    cudaEvent_t evA, evB, evC, evD;
    cudaEventCreateWithFlags(&evA, cudaEventDisableTiming);
    cudaEventCreateWithFlags(&evB, cudaEventDisableTiming);
    cudaEventCreateWithFlags(&evC, cudaEventDisableTiming);
    cudaEventCreateWithFlags(&evD, cudaEventDisableTiming);
    cudaStream_t s0 = 0;

    // ---- main stream: hs convert ----
    cvt(hs, hs16, (long)NTOK_ * H_, s0);
    cudaEventRecord(evA, s0);
    cudaStreamWaitEvent(s2, evA, 0);

    // ---- side stream: independent prep + ckv projection ----
    transp_f32f16<<<dim3(DATT_/32, H_/32, 1), 256, 0, s2>>>(Wkv_a, WkvaT, DATT_, H_, 0, 0);
    transp_f32f16<<<dim3(H_/32, H_/32, 1), 256, 0, s2>>>(Wo, WoT, H_, H_, 0, 0);
    cvt(Wkv_b, Wkvb16, (long)NH_ * 256 * RANK_, s2);
    hgemm_t<__half>(hs16, WkvaT, ckvraw16, NTOK_, DATT_, H_, H_, H_, DATT_, 1, 1,
                    0,0,0,0,0,0, s2);
    cudaEventRecord(evB, s2);

    // ---- main stream: Wq transpose + q projection (overlaps side stream) ----
    transp_f32f16<<<dim3((NH_*QHD_)/32, H_/32, 1), 256, 0, s0>>>(Wq, WqT, NH_*QHD_, H_, 0, 0);
    hgemm_t<__half>(hs16, WqT, q16, NTOK_, NH_*QHD_, H_, H_, H_, NH_*QHD_, 1, 1,
                    0,0,0,0,0,0, s0);

    // ---- join: rmsrope needs q16 (s0) + ckvraw16 (s2) ----
    cudaStreamWaitEvent(s0, evB, 0);
    rmsrope_kernel<<<NTOK_, 128, 0, s0>>>(q16, ckvraw16, pos, cosc, sinc, lnw, ckv16, keff16);
    cudaEventRecord(evC, s0);

    // ---- fork: keff on s0, veff on s2 ----
    hgemm_t<__half>(ckv16, Wkvb16, keff16, S_, NOPE_, RANK_, RANK_, RANK_, QHD_,
          B_*NH_, NH_,
          (long)S_*RANK_, 0,
          0, (long)256*RANK_,
          (long)NH_*S_*QHD_, (long)S_*QHD_, s0);

    cudaStreamWaitEvent(s2, evC, 0);
    hgemm_t<__half>(Wkvb16 + (long)NOPE_*RANK_, ckv16, veffT, VDIM_, S_, RANK_,
          RANK_, RANK_, S_,
          B_*NH_, NH_,
          0, (long)256*RANK_,
          (long)S_*RANK_, 0,
          (long)NH_*VDIM_*S_, (long)VDIM_*S_, s2);
    cudaEventRecord(evD, s2);
    cudaStreamWaitEvent(s0, evD, 0);

    // ---- fused flash attention (single launch, heavy-first) ----
    {
        int sm = (3*128*PADQ + 2*128*PADV) * 2;   // 223232 bytes
        cudaFuncSetAttribute(flash_kernel, cudaFuncAttributeMaxDynamicSharedMemorySize, sm);
        dim3 g(NBLK, 1, B_*NH_);
        flash_kernel<<<g, 256, sm, s0>>>(q16, keff16, veffT, attn16);
    }

    // ---- final projection ----
    hgemm_t<float>(attn16, WoT, out, NTOK_, H_, NH_*VDIM_, NH_*VDIM_, NH_*VDIM_, H_, 1, 1,
                   0,0,0,0,0,0, s0);
}

// round 15
// speedup vs baseline: 1.0342x; 1.0037x over previous
#include <cuda_runtime.h>
#include <cuda_fp16.h>
#include <math.h>
#include <stdint.h>

// Problem constants
#define B_    2
#define S_    2048
#define H_    2048
#define NH_   16
#define NOPE_ 128
#define ROPE_ 64
#define VDIM_ 128
#define RANK_ 512
#define QHD_  192
#define DATT_ 576
#define NTOK_ (B_*S_)

// ---------------- scratch ----------------
__device__ unsigned short g_hs16[(long)NTOK_ * H_];
__device__ unsigned short g_WqT16[(long)(NH_*QHD_) * H_];
__device__ unsigned short g_WkvaT16[(long)DATT_ * H_];
__device__ unsigned short g_WoT16[(long)H_ * (NH_*VDIM_)];
__device__ unsigned short g_Wkvb16[(long)NH_ * 256 * RANK_];
__device__ unsigned short g_q16[(long)NTOK_ * (NH_*QHD_)];       // roped in place
__device__ unsigned short g_ckvraw16[(long)NTOK_ * DATT_];
__device__ unsigned short g_ckv16[(long)NTOK_ * RANK_];          // rms-normed
__device__ unsigned short g_keff16[(long)B_*NH_*S_ * QHD_];      // [ckv@qabs^T | k_pe]
__device__ unsigned short g_veffT16[(long)B_*NH_ * VDIM_ * S_];  // out_absorb @ ckv^T
__device__ unsigned short g_attn16[(long)NTOK_ * (NH_*VDIM_)];

// ---------------- helpers ----------------
__device__ __forceinline__ uint32_t su32(const void* p){ return (uint32_t)__cvta_generic_to_shared((void*)p); }

#define CP_ASYNC16(dst, src) asm volatile("cp.async.cg.shared.global [%0], [%1], 16;" :: "r"(dst), "l"(src))
#define CP_COMMIT()          asm volatile("cp.async.commit_group;" ::: "memory")
#define CP_WAIT(n)           asm volatile("cp.async.wait_group %0;" :: "n"(n) : "memory")

__device__ __forceinline__ void ldmx4(uint32_t& r0, uint32_t& r1, uint32_t& r2, uint32_t& r3, uint32_t addr){
    asm volatile("ldmatrix.sync.aligned.m8n8.x4.shared.b16 {%0,%1,%2,%3}, [%4];"
                 : "=r"(r0), "=r"(r1), "=r"(r2), "=r"(r3) : "r"(addr));
}
__device__ __forceinline__ void mma16816(float* c, const uint32_t* a, const uint32_t* b){
    asm volatile("mma.sync.aligned.m16n8k16.row.col.f32.f16.f16.f32 "
                 "{%0,%1,%2,%3}, {%4,%5,%6,%7}, {%8,%9}, {%0,%1,%2,%3};"
                 : "+f"(c[0]), "+f"(c[1]), "+f"(c[2]), "+f"(c[3])
                 : "r"(a[0]), "r"(a[1]), "r"(a[2]), "r"(a[3]), "r"(b[0]), "r"(b[1]));
}
__device__ __forceinline__ uint32_t packh2(float a, float b){
    __half2 h = __floats2half2_rn(a, b);
    return *reinterpret_cast<uint32_t*>(&h);
}

// ---------------- HMMA NT GEMM: C = A(f16,MxK) @ B(f16,NxK)^T ----------------
#define KT_   64
#define PAD_  72

template<int BN, typename CT>
__global__ __launch_bounds__(256, 2)
void hgemm_mma(const __half* __restrict__ A, const __half* __restrict__ B, CT* __restrict__ C,
               int K, int lda, int ldb, int ldc,
               int zdiv, long aOut, long aIn, long bOut, long bIn, long cOut, long cIn)
{
    constexpr int NT = BN / 16;
    constexpr int ASTR = 128 * PAD_ * 2;
    constexpr int BSTR = BN * PAD_ * 2;
    extern __shared__ char smem[];
    const uint32_t saBase = su32(smem);
    const uint32_t sbBase = saBase + 3 * ASTR;

    const int bm = blockIdx.y * 128;
    const int bn = blockIdx.x * BN;

    const int z = blockIdx.z;
    A += (long)(z / zdiv) * aOut + (long)(z % zdiv) * aIn;
    B += (long)(z / zdiv) * bOut + (long)(z % zdiv) * bIn;
    C += (long)(z / zdiv) * cOut + (long)(z % zdiv) * cIn;

    const int NC = K / KT_;

    const int tid = threadIdx.x;
    const int lane = tid & 31, wp = tid >> 5;
    const int mw = wp >> 1;
    const int nw = wp & 1;
    constexpr int WN = BN / 2;

    const int arow = mw * 32 + (lane & 15);
    const int acol = (lane >> 4) * 8;
    const int brow = nw * WN + (lane & 7) + ((lane >> 4) << 3);
    const int bcol = ((lane >> 3) & 1) * 8;

    auto load_async = [&](int kt, int s){
        uint32_t sa = saBase + s * ASTR;
#pragma unroll
        for (int i = 0; i < 4; i++) {
            int v = tid + i * 256;
            int r = v >> 3, c8 = (v & 7) * 8;
            CP_ASYNC16(sa + (r * PAD_ + c8) * 2, A + (long)(bm + r) * lda + kt + c8);
        }
        uint32_t sb = sbBase + s * BSTR;
#pragma unroll
        for (int i = 0; i < BN / 32; i++) {
            int v = tid + i * 256;
            int r = v >> 3, c8 = (v & 7) * 8;
            CP_ASYNC16(sb + (r * PAD_ + c8) * 2, B + (long)(bn + r) * ldb + kt + c8);
        }
    };

    float acc[2][NT][4];
#pragma unroll
    for (int mt = 0; mt < 2; mt++)
#pragma unroll
        for (int nt = 0; nt < NT; nt++)
#pragma unroll
            for (int i = 0; i < 4; i++) acc[mt][nt][i] = 0.f;

    load_async(0, 0);  CP_COMMIT();
    if (NC > 1) load_async(KT_, 1);
    CP_COMMIT();

    for (int c = 0; c < NC; c++) {
        if (c == NC - 1) { CP_WAIT(0); } else { CP_WAIT(1); }
        __syncthreads();
        if (c + 2 < NC) { load_async((c + 2) * KT_, (c + 2) % 3); CP_COMMIT(); }

        const int s = c - (c / 3) * 3;
        const uint32_t sa = saBase + s * ASTR;
        const uint32_t sb = sbBase + s * BSTR;

#pragma unroll
        for (int kk = 0; kk < KT_; kk += 16) {
            uint32_t afr[2][4];
#pragma unroll
            for (int mt = 0; mt < 2; mt++)
                ldmx4(afr[mt][0], afr[mt][1], afr[mt][2], afr[mt][3],
                      sa + (uint32_t)(((arow + mt * 16) * PAD_ + kk + acol) * 2));
            uint32_t bfr[NT][2];
#pragma unroll
            for (int p = 0; p < NT / 2; p++)
                ldmx4(bfr[2*p][0], bfr[2*p][1], bfr[2*p+1][0], bfr[2*p+1][1],
                      sb + (uint32_t)(((brow + p * 16) * PAD_ + kk + bcol) * 2));
#pragma unroll
            for (int mt = 0; mt < 2; mt++)
#pragma unroll
                for (int nt = 0; nt < NT; nt++)
                    mma16816(acc[mt][nt], afr[mt], bfr[nt]);
        }
    }

    const int g = lane >> 2, tg = lane & 3;
#pragma unroll
    for (int mt = 0; mt < 2; mt++) {
        const int row = bm + mw * 32 + mt * 16 + g;
#pragma unroll
        for (int nt = 0; nt < NT; nt++) {
            const int col = bn + nw * WN + nt * 8 + tg * 2;
            if constexpr (sizeof(CT) == 2) {
                *reinterpret_cast<__half2*>((__half*)C + (long)row * ldc + col) =
                    __floats2half2_rn(acc[mt][nt][0], acc[mt][nt][1]);
                *reinterpret_cast<__half2*>((__half*)C + (long)(row + 8) * ldc + col) =
                    __floats2half2_rn(acc[mt][nt][2], acc[mt][nt][3]);
            } else {
                *reinterpret_cast<float2*>((float*)C + (long)row * ldc + col) =
                    make_float2(acc[mt][nt][0], acc[mt][nt][1]);
                *reinterpret_cast<float2*>((float*)C + (long)(row + 8) * ldc + col) =
                    make_float2(acc[mt][nt][2], acc[mt][nt][3]);
            }
        }
    }
}

// ---------------- fused flash attention: scores + softmax + PV ----------------
#define FBLK  128
#define NBLK  (S_/FBLK)   // 16
#define PADQ  200
#define PADV  136

__global__ __launch_bounds__(256, 1)
void flash_kernel(const __half* __restrict__ q, const __half* __restrict__ keff,
                  const __half* __restrict__ veff, __half* __restrict__ attn)
{
    extern __shared__ char smem[];
    const uint32_t sQa = su32(smem);
    const uint32_t sKa[2] = { sQa + 128*PADQ*2, sQa + 2*128*PADQ*2 };
    const uint32_t sVa[2] = { sQa + 3*128*PADQ*2, sQa + 3*128*PADQ*2 + 128*PADV*2 };

    const int z = blockIdx.z;                  // bh
    const int b = z >> 4, h = z & (NH_-1);
    const int iblk = (NBLK - 1) - blockIdx.x;  // heavy blocks first

    const int tid = threadIdx.x, lane = tid & 31, w = tid >> 5;
    const int g = lane >> 2, tg = lane & 3;
    const int m0r = w * 16;

    const __half* Qbase = q + (long)(b*S_ + iblk*FBLK) * (NH_*QHD_) + h*QHD_;
    const __half* Kbase = keff + (long)z * S_ * QHD_;
    const __half* Vbase = veff + (long)z * VDIM_ * S_;

    for (int v = tid; v < 128*24; v += 256) {
        int r = v / 24, c = v % 24;
        CP_ASYNC16(sQa + (r*PADQ + c*8)*2, Qbase + (long)r*(NH_*QHD_) + c*8);
    }
    auto loadK = [&](int j, int s){
        const __half* kb = Kbase + (long)j*FBLK*QHD_;
        for (int v = tid; v < 128*24; v += 256) {
            int r = v / 24, c = v % 24;
            CP_ASYNC16(sKa[s] + (r*PADQ + c*8)*2, kb + (long)r*QHD_ + c*8);
        }
    };
    auto loadV = [&](int j, int s){
        const __half* vb = Vbase + j*FBLK;
        for (int v = tid; v < 128*16; v += 256) {
            int r = v >> 4, c = v & 15;
            CP_ASYNC16(sVa[s] + (r*PADV + c*8)*2, vb + (long)r*S_ + c*8);
        }
    };
    loadK(0, 0); loadV(0, 0); CP_COMMIT();

    float Oacc[16][4];
#pragma unroll
    for (int nt = 0; nt < 16; nt++)
#pragma unroll
        for (int i = 0; i < 4; i++) Oacc[nt][i] = 0.f;
    float m0 = -1e30f, m1 = -1e30f, l0 = 0.f, l1 = 0.f;
    const float scale = 0.07216878364870322f;   // 192^-0.5

    const int arow = lane & 15;
    const int acol = (lane >> 4) * 8;
    const int brow = (lane & 7) + ((lane >> 4) << 3);
    const int bcol = ((lane >> 3) & 1) * 8;

    for (int j = 0; j <= iblk; j++) {
        const int s = j & 1;
        CP_WAIT(0);
        __syncthreads();
        if (j < iblk) { loadK(j+1, s^1); loadV(j+1, s^1); CP_COMMIT(); }

        // ---- S = Q @ Keff_j^T ----
        float Sacc[16][4];
#pragma unroll
        for (int nt = 0; nt < 16; nt++)
#pragma unroll
            for (int i = 0; i < 4; i++) Sacc[nt][i] = 0.f;

#pragma unroll
        for (int kk = 0; kk < QHD_; kk += 16) {
            uint32_t afr[4];
            ldmx4(afr[0], afr[1], afr[2], afr[3],
                  sQa + (uint32_t)(((m0r + arow)*PADQ + kk + acol)*2));
            uint32_t bfr[16][2];
#pragma unroll
            for (int p = 0; p < 8; p++)
                ldmx4(bfr[2*p][0], bfr[2*p][1], bfr[2*p+1][0], bfr[2*p+1][1],
                      sKa[s] + (uint32_t)(((p*16 + brow)*PADQ + kk + bcol)*2));
#pragma unroll
            for (int nt = 0; nt < 16; nt++)
                mma16816(Sacc[nt], afr, bfr[nt]);
        }

        // ---- causal mask on diagonal block ----
        if (j == iblk) {
            const int r0 = m0r + g, r1 = r0 + 8;
#pragma unroll
            for (int nt = 0; nt < 16; nt++) {
                const int c0 = nt*8 + tg*2;
                if (c0     > r0) Sacc[nt][0] = -1e30f;
                if (c0 + 1 > r0) Sacc[nt][1] = -1e30f;
                if (c0     > r1) Sacc[nt][2] = -1e30f;
                if (c0 + 1 > r1) Sacc[nt][3] = -1e30f;
            }
        }

        // ---- online softmax ----
        float bm0 = -1e30f, bm1 = -1e30f;
#pragma unroll
        for (int nt = 0; nt < 16; nt++) {
            bm0 = fmaxf(bm0, fmaxf(Sacc[nt][0], Sacc[nt][1]));
            bm1 = fmaxf(bm1, fmaxf(Sacc[nt][2], Sacc[nt][3]));
        }
        bm0 = fmaxf(bm0, __shfl_xor_sync(0xffffffffu, bm0, 1));
        bm0 = fmaxf(bm0, __shfl_xor_sync(0xffffffffu, bm0, 2));
        bm1 = fmaxf(bm1, __shfl_xor_sync(0xffffffffu, bm1, 1));
        bm1 = fmaxf(bm1, __shfl_xor_sync(0xffffffffu, bm1, 2));
        const float mn0 = fmaxf(m0, bm0), mn1 = fmaxf(m1, bm1);
        const float corr0 = __expf((m0 - mn0) * scale);
        const float corr1 = __expf((m1 - mn1) * scale);
        m0 = mn0; m1 = mn1;
        l0 *= corr0; l1 *= corr1;
#pragma unroll
        for (int nt = 0; nt < 16; nt++) {
            Oacc[nt][0] *= corr0; Oacc[nt][1] *= corr0;
            Oacc[nt][2] *= corr1; Oacc[nt][3] *= corr1;
        }

        // ---- P = exp((S-m)*scale); O += P @ Veff_j ----
#pragma unroll
        for (int t = 0; t < 8; t++) {
            const float e00 = __expf((Sacc[2*t  ][0] - m0) * scale);
            const float e01 = __expf((Sacc[2*t  ][1] - m0) * scale);
            const float e02 = __expf((Sacc[2*t  ][2] - m1) * scale);
            const float e03 = __expf((Sacc[2*t  ][3] - m1) * scale);
            const float e10 = __expf((Sacc[2*t+1][0] - m0) * scale);
            const float e11 = __expf((Sacc[2*t+1][1] - m0) * scale);
            const float e12 = __expf((Sacc[2*t+1][2] - m1) * scale);
            const float e13 = __expf((Sacc[2*t+1][3] - m1) * scale);
            l0 += e00 + e01 + e10 + e11;
            l1 += e02 + e03 + e12 + e13;
            uint32_t pa[4];
            pa[0] = packh2(e00, e01);
            pa[1] = packh2(e02, e03);
            pa[2] = packh2(e10, e11);
            pa[3] = packh2(e12, e13);
            uint32_t bfr[16][2];
#pragma unroll
            for (int p = 0; p < 8; p++)
                ldmx4(bfr[2*p][0], bfr[2*p][1], bfr[2*p+1][0], bfr[2*p+1][1],
                      sVa[s] + (uint32_t)(((p*16 + brow)*PADV + t*16 + bcol)*2));
#pragma unroll
            for (int nt = 0; nt < 16; nt++)
                mma16816(Oacc[nt], pa, bfr[nt]);
        }
    }

    // ---- finalize ----
    l0 += __shfl_xor_sync(0xffffffffu, l0, 1);
    l0 += __shfl_xor_sync(0xffffffffu, l0, 2);
    l1 += __shfl_xor_sync(0xffffffffu, l1, 1);
    l1 += __shfl_xor_sync(0xffffffffu, l1, 2);
    const float inv0 = 1.0f / l0, inv1 = 1.0f / l1;

    const long s0 = (long)(b*S_ + iblk*FBLK + m0r + g);
    __half* o0 = attn + (s0 * NH_ + h) * VDIM_;
    __half* o1 = attn + ((s0 + 8) * NH_ + h) * VDIM_;
#pragma unroll
    for (int nt = 0; nt < 16; nt++) {
        const int col = nt*8 + tg*2;
        *reinterpret_cast<__half2*>(o0 + col) = __floats2half2_rn(Oacc[nt][0]*inv0, Oacc[nt][1]*inv0);
        *reinterpret_cast<__half2*>(o1 + col) = __floats2half2_rn(Oacc[nt][2]*inv1, Oacc[nt][3]*inv1);
    }
}

// ---------------- converts ----------------
__global__ __launch_bounds__(256) void f32tof16(const float* __restrict__ in, __half* __restrict__ out, long n4)
{
    long i = blockIdx.x * 256L + threadIdx.x;
    long stride = (long)gridDim.x * 256;
    for (; i < n4; i += stride) {
        float4 v = reinterpret_cast<const float4*>(in)[i];
        reinterpret_cast<__half2*>(out)[2*i]   = __floats2half2_rn(v.x, v.y);
        reinterpret_cast<__half2*>(out)[2*i+1] = __floats2half2_rn(v.z, v.w);
    }
}

__global__ __launch_bounds__(256) void transp_f32f16(const float* __restrict__ in, __half* __restrict__ out,
                                                     int ldin, int ldout, long inB, long outB)
{
    __shared__ float t[32][33];
    const int z = blockIdx.z;
    in += (long)z * inB; out += (long)z * outB;
    const int r0 = blockIdx.y * 32, c0 = blockIdx.x * 32;
    const int x = threadIdx.x & 31, y = threadIdx.x >> 5;
#pragma unroll
    for (int i = 0; i < 32; i += 8)
        t[y + i][x] = in[(long)(r0 + y + i) * ldin + c0 + x];
    __syncthreads();
#pragma unroll
    for (int i = 0; i < 32; i += 8)
        out[(long)(c0 + y + i) * ldout + r0 + x] = __float2half_rn(t[x][y + i]);
}

// ---------------- rms-norm + k_pe rope (ckv side only; no q dependency) ----------------
__global__ __launch_bounds__(128)
void rmsC_kernel(const __half* __restrict__ ckvraw,
                 const int* __restrict__ pos_ids, const float* __restrict__ cosc,
                 const float* __restrict__ sinc, const float* __restrict__ lnw,
                 __half* __restrict__ ckv16, __half* __restrict__ keff)
{
    const int t = blockIdx.x;
    const int b = t / S_, s = t - b * S_;
    const __half* cv = ckvraw + (long)t * DATT_;

    __shared__ float red[4];
    __shared__ __half kpe[64];
    float ss = 0.f;
    for (int i = threadIdx.x; i < RANK_; i += 128) { float v = __half2float(cv[i]); ss += v * v; }
#pragma unroll
    for (int o = 16; o; o >>= 1) ss += __shfl_xor_sync(0xffffffffu, ss, o);
    if ((threadIdx.x & 31) == 0) red[threadIdx.x >> 5] = ss;
    __syncthreads();
    const float inv = rsqrtf((red[0] + red[1] + red[2] + red[3]) * (1.0f / RANK_) + 1e-6f);

    __half* kd = ckv16 + (long)t * RANK_;
    for (int i = threadIdx.x; i < RANK_; i += 128)
        kd[i] = __float2half_rn(__half2float(cv[i]) * inv * lnw[i]);

    const int pos = pos_ids[t];
    const float* cr = cosc + (long)pos * ROPE_;
    const float* sr = sinc + (long)pos * ROPE_;

    if (threadIdx.x < 32) {
        const int j = threadIdx.x;
        const float c = cr[j], sn = sr[j];
        const float e = __half2float(cv[RANK_ + 2*j]), o = __half2float(cv[RANK_ + 2*j + 1]);
        kpe[j]      = __float2half_rn(e * c - o * sn);
        kpe[32 + j] = __float2half_rn(o * c + e * sn);
    }
    __syncthreads();
    {   // 16 heads x 8 uint4 = 128 threads, one 16B store each
        const int h = threadIdx.x >> 3, c4 = threadIdx.x & 7;
        __half* kb = keff + ((long)(b * NH_ + h) * S_ + s) * QHD_ + NOPE_;
        reinterpret_cast<uint4*>(kb)[c4] = reinterpret_cast<const uint4*>(kpe)[c4];
    }
}

// ---------------- q_pe rope in place ----------------
__global__ __launch_bounds__(128)
void qpe_kernel(__half* __restrict__ q16, const int* __restrict__ pos_ids,
                const float* __restrict__ cosc, const float* __restrict__ sinc)
{
    const int t = blockIdx.x;
    const int pos = pos_ids[t];
    const float* cr = cosc + (long)pos * ROPE_;
    const float* sr = sinc + (long)pos * ROPE_;

    for (int p = threadIdx.x; p < NH_ * 32; p += 128) {
        const int h = p >> 5, j = p & 31;
        const float c = cr[j], sn = sr[j];
        __half* qs = q16 + (long)t * (NH_*QHD_) + h * QHD_ + NOPE_;
        const float e = __half2float(qs[2*j]), o = __half2float(qs[2*j + 1]);
        __syncwarp();
        qs[j]      = __float2half_rn(e * c - o * sn);
        qs[32 + j] = __float2half_rn(o * c + e * sn);
    }
}

// ---------------- host ----------------
template<typename CT>
static void hgemm_t(const __half* A, const __half* B, CT* C,
                    int M, int N, int K, int lda, int ldb, int ldc, int Z, int zdiv,
                    long aO, long aI, long bO, long bI, long cO, long cI,
                    cudaStream_t st)
{
    if (N % 128 == 0) {
        int sm = 3 * (128 + 128) * PAD_ * 2;
        cudaFuncSetAttribute(hgemm_mma<128, CT>, cudaFuncAttributeMaxDynamicSharedMemorySize, sm);
        dim3 g(N / 128, M / 128, Z);
        hgemm_mma<128, CT><<<g, 256, sm, st>>>(A, B, C, K, lda, ldb, ldc, zdiv, aO, aI, bO, bI, cO, cI);
    } else {
        int sm = 3 * (128 + 64) * PAD_ * 2;
        cudaFuncSetAttribute(hgemm_mma<64, CT>, cudaFuncAttributeMaxDynamicSharedMemorySize, sm);
        dim3 g(N / 64, M / 128, Z);
        hgemm_mma<64, CT><<<g, 256, sm, st>>>(A, B, C, K, lda, ldb, ldc, zdiv, aO, aI, bO, bI, cO, cI);
    }
}

static void cvt(const float* in, __half* out, long n, cudaStream_t st)
{
    long n4 = n / 4;
    int blocks = (int)((n4 + 255) / 256); if (blocks > 8192) blocks = 8192;
    f32tof16<<<blocks, 256, 0, st>>>(in, out, n4);
}

extern "C" void kernel_launch(void* const* d_in, const int* in_sizes, int n_in,
                              void* d_out, int out_size)
{
    const float* hs    = (const float*)d_in[0];
    const int*   pos   = (const int*)d_in[2];
    const float* cosc  = (const float*)d_in[3];
    const float* sinc  = (const float*)d_in[4];
    const float* Wq    = (const float*)d_in[5];
    const float* Wkv_a = (const float*)d_in[6];
    const float* lnw   = (const float*)d_in[7];
    const float* Wkv_b = (const float*)d_in[8];
    const float* Wo    = (const float*)d_in[9];
    float* out = (float*)d_out;

    __half *hs16, *WqT, *WkvaT, *WoT, *Wkvb16, *q16, *ckvraw16, *ckv16, *keff16, *veffT, *attn16;
    cudaGetSymbolAddress((void**)&hs16, g_hs16);
    cudaGetSymbolAddress((void**)&WqT, g_WqT16);
    cudaGetSymbolAddress((void**)&WkvaT, g_WkvaT16);
    cudaGetSymbolAddress((void**)&WoT, g_WoT16);
    cudaGetSymbolAddress((void**)&Wkvb16, g_Wkvb16);
    cudaGetSymbolAddress((void**)&q16, g_q16);
    cudaGetSymbolAddress((void**)&ckvraw16, g_ckvraw16);
    cudaGetSymbolAddress((void**)&ckv16, g_ckv16);
    cudaGetSymbolAddress((void**)&keff16, g_keff16);
    cudaGetSymbolAddress((void**)&veffT, g_veffT16);
    cudaGetSymbolAddress((void**)&attn16, g_attn16);

    // Legal fork: s2's first op waits on evA recorded in the capturing stream.
    cudaStream_t s2;
    cudaStreamCreateWithFlags(&s2, cudaStreamNonBlocking);
    cudaEvent_t evA, evB, evD;
    cudaEventCreateWithFlags(&evA, cudaEventDisableTiming);
    cudaEventCreateWithFlags(&evB, cudaEventDisableTiming);
    cudaEventCreateWithFlags(&evD, cudaEventDisableTiming);
    cudaStream_t s0 = 0;

    // ---- s0: hs convert, then fork ----
    cvt(hs, hs16, (long)NTOK_ * H_, s0);
    cudaEventRecord(evA, s0);
    cudaStreamWaitEvent(s2, evA, 0);

    // ---- s2: kv-side prep + ckvproj + rmsC + veff (all q-independent) ----
    transp_f32f16<<<dim3(DATT_/32, H_/32, 1), 256, 0, s2>>>(Wkv_a, WkvaT, DATT_, H_, 0, 0);
    transp_f32f16<<<dim3(H_/32, H_/32, 1), 256, 0, s2>>>(Wo, WoT, H_, H_, 0, 0);
    cvt(Wkv_b, Wkvb16, (long)NH_ * 256 * RANK_, s2);
    hgemm_t<__half>(hs16, WkvaT, ckvraw16, NTOK_, DATT_, H_, H_, H_, DATT_, 1, 1,
                    0,0,0,0,0,0, s2);
    rmsC_kernel<<<NTOK_, 128, 0, s2>>>(ckvraw16, pos, cosc, sinc, lnw, ckv16, keff16);
    cudaEventRecord(evB, s2);                       // ckv16 + keff k_pe + Wkvb16 + WoT ready
    hgemm_t<__half>(Wkvb16 + (long)NOPE_*RANK_, ckv16, veffT, VDIM_, S_, RANK_,
          RANK_, RANK_, S_,
          B_*NH_, NH_,
          0, (long)256*RANK_,
          (long)S_*RANK_, 0,
          (long)NH_*VDIM_*S_, (long)VDIM_*S_, s2);
    cudaEventRecord(evD, s2);

    // ---- s0: WqT + q projection + q_pe rope ----
    transp_f32f16<<<dim3((NH_*QHD_)/32, H_/32, 1), 256, 0, s0>>>(Wq, WqT, NH_*QHD_, H_, 0, 0);
    hgemm_t<__half>(hs16, WqT, q16, NTOK_, NH_*QHD_, H_, H_, H_, NH_*QHD_, 1, 1,
                    0,0,0,0,0,0, s0);
    qpe_kernel<<<NTOK_, 128, 0, s0>>>(q16, pos, cosc, sinc);

    // ---- s0: keff (needs ckv16 from s2) ----
    cudaStreamWaitEvent(s0, evB, 0);
    hgemm_t<__half>(ckv16, Wkvb16, keff16, S_, NOPE_, RANK_, RANK_, RANK_, QHD_,
          B_*NH_, NH_,
          (long)S_*RANK_, 0,
          0, (long)256*RANK_,
          (long)NH_*S_*QHD_, (long)S_*QHD_, s0);

    // ---- join: flash needs veff from s2 ----
    cudaStreamWaitEvent(s0, evD, 0);
    {
        int sm = (3*128*PADQ + 2*128*PADV) * 2;   // 223232 bytes
        cudaFuncSetAttribute(flash_kernel, cudaFuncAttributeMaxDynamicSharedMemorySize, sm);
        dim3 g(NBLK, 1, B_*NH_);
        flash_kernel<<<g, 256, sm, s0>>>(q16, keff16, veffT, attn16);
    }

    // ---- final projection (WoT produced before evB on s2) ----
    hgemm_t<float>(attn16, WoT, out, NTOK_, H_, NH_*VDIM_, NH_*VDIM_, NH_*VDIM_, H_, 1, 1,
                   0,0,0,0,0,0, s0);
}

// round 16
// speedup vs baseline: 1.0436x; 1.0091x over previous
#include <cuda_runtime.h>
#include <cuda_fp16.h>
#include <math.h>
#include <stdint.h>

// Problem constants
#define B_    2
#define S_    2048
#define H_    2048
#define NH_   16
#define NOPE_ 128
#define ROPE_ 64
#define VDIM_ 128
#define RANK_ 512
#define QHD_  192
#define DATT_ 576
#define NTOK_ (B_*S_)

// ---------------- scratch ----------------
__device__ unsigned short g_hs16[(long)NTOK_ * H_];
__device__ unsigned short g_WqT16[(long)(NH_*QHD_) * H_];
__device__ unsigned short g_WkvaT16[(long)DATT_ * H_];
__device__ unsigned short g_WoT16[(long)H_ * (NH_*VDIM_)];
__device__ unsigned short g_Wkvb16[(long)NH_ * 256 * RANK_];
__device__ unsigned short g_q16[(long)NTOK_ * (NH_*QHD_)];       // roped in place
__device__ unsigned short g_ckvraw16[(long)NTOK_ * DATT_];
__device__ unsigned short g_ckv16[(long)NTOK_ * RANK_];          // rms-normed
__device__ unsigned short g_keff16[(long)B_*NH_*S_ * QHD_];      // [ckv@qabs^T | k_pe]
__device__ unsigned short g_veffT16[(long)B_*NH_ * VDIM_ * S_];  // out_absorb @ ckv^T
__device__ unsigned short g_attn16[(long)NTOK_ * (NH_*VDIM_)];

// ---------------- helpers ----------------
__device__ __forceinline__ uint32_t su32(const void* p){ return (uint32_t)__cvta_generic_to_shared((void*)p); }

#define CP_ASYNC16(dst, src) asm volatile("cp.async.cg.shared.global [%0], [%1], 16;" :: "r"(dst), "l"(src))
#define CP_COMMIT()          asm volatile("cp.async.commit_group;" ::: "memory")
#define CP_WAIT(n)           asm volatile("cp.async.wait_group %0;" :: "n"(n) : "memory")

__device__ __forceinline__ void ldmx4(uint32_t& r0, uint32_t& r1, uint32_t& r2, uint32_t& r3, uint32_t addr){
    asm volatile("ldmatrix.sync.aligned.m8n8.x4.shared.b16 {%0,%1,%2,%3}, [%4];"
                 : "=r"(r0), "=r"(r1), "=r"(r2), "=r"(r3) : "r"(addr));
}
__device__ __forceinline__ void mma16816(float* c, const uint32_t* a, const uint32_t* b){
    asm volatile("mma.sync.aligned.m16n8k16.row.col.f32.f16.f16.f32 "
                 "{%0,%1,%2,%3}, {%4,%5,%6,%7}, {%8,%9}, {%0,%1,%2,%3};"
                 : "+f"(c[0]), "+f"(c[1]), "+f"(c[2]), "+f"(c[3])
                 : "r"(a[0]), "r"(a[1]), "r"(a[2]), "r"(a[3]), "r"(b[0]), "r"(b[1]));
}
__device__ __forceinline__ uint32_t packh2(float a, float b){
    __half2 h = __floats2half2_rn(a, b);
    return *reinterpret_cast<uint32_t*>(&h);
}

// ---------------- HMMA NT GEMM: C = A(f16,MxK) @ B(f16,NxK)^T ----------------
#define KT_   64
#define PAD_  72

template<int BN, typename CT>
__global__ __launch_bounds__(256, 2)
void hgemm_mma(const __half* __restrict__ A, const __half* __restrict__ B, CT* __restrict__ C,
               int K, int lda, int ldb, int ldc,
               int zdiv, long aOut, long aIn, long bOut, long bIn, long cOut, long cIn)
{
    constexpr int NT = BN / 16;
    constexpr int ASTR = 128 * PAD_ * 2;
    constexpr int BSTR = BN * PAD_ * 2;
    extern __shared__ char smem[];
    const uint32_t saBase = su32(smem);
    const uint32_t sbBase = saBase + 3 * ASTR;

    const int bm = blockIdx.y * 128;
    const int bn = blockIdx.x * BN;

    const int z = blockIdx.z;
    A += (long)(z / zdiv) * aOut + (long)(z % zdiv) * aIn;
    B += (long)(z / zdiv) * bOut + (long)(z % zdiv) * bIn;
    C += (long)(z / zdiv) * cOut + (long)(z % zdiv) * cIn;

    const int NC = K / KT_;

    const int tid = threadIdx.x;
    const int lane = tid & 31, wp = tid >> 5;
    const int mw = wp >> 1;
    const int nw = wp & 1;
    constexpr int WN = BN / 2;

    const int arow = mw * 32 + (lane & 15);
    const int acol = (lane >> 4) * 8;
    const int brow = nw * WN + (lane & 7) + ((lane >> 4) << 3);
    const int bcol = ((lane >> 3) & 1) * 8;

    auto load_async = [&](int kt, int s){
        uint32_t sa = saBase + s * ASTR;
#pragma unroll
        for (int i = 0; i < 4; i++) {
            int v = tid + i * 256;
            int r = v >> 3, c8 = (v & 7) * 8;
            CP_ASYNC16(sa + (r * PAD_ + c8) * 2, A + (long)(bm + r) * lda + kt + c8);
        }
        uint32_t sb = sbBase + s * BSTR;
#pragma unroll
        for (int i = 0; i < BN / 32; i++) {
            int v = tid + i * 256;
            int r = v >> 3, c8 = (v & 7) * 8;
            CP_ASYNC16(sb + (r * PAD_ + c8) * 2, B + (long)(bn + r) * ldb + kt + c8);
        }
    };

    float acc[2][NT][4];
#pragma unroll
    for (int mt = 0; mt < 2; mt++)
#pragma unroll
        for (int nt = 0; nt < NT; nt++)
#pragma unroll
            for (int i = 0; i < 4; i++) acc[mt][nt][i] = 0.f;

    load_async(0, 0);  CP_COMMIT();
    if (NC > 1) load_async(KT_, 1);
    CP_COMMIT();

    for (int c = 0; c < NC; c++) {
        if (c == NC - 1) { CP_WAIT(0); } else { CP_WAIT(1); }
        __syncthreads();
        if (c + 2 < NC) { load_async((c + 2) * KT_, (c + 2) % 3); CP_COMMIT(); }

        const int s = c - (c / 3) * 3;
        const uint32_t sa = saBase + s * ASTR;
        const uint32_t sb = sbBase + s * BSTR;

#pragma unroll
        for (int kk = 0; kk < KT_; kk += 16) {
            uint32_t afr[2][4];
#pragma unroll
            for (int mt = 0; mt < 2; mt++)
                ldmx4(afr[mt][0], afr[mt][1], afr[mt][2], afr[mt][3],
                      sa + (uint32_t)(((arow + mt * 16) * PAD_ + kk + acol) * 2));
            uint32_t bfr[NT][2];
#pragma unroll
            for (int p = 0; p < NT / 2; p++)
                ldmx4(bfr[2*p][0], bfr[2*p][1], bfr[2*p+1][0], bfr[2*p+1][1],
                      sb + (uint32_t)(((brow + p * 16) * PAD_ + kk + bcol) * 2));
#pragma unroll
            for (int mt = 0; mt < 2; mt++)
#pragma unroll
                for (int nt = 0; nt < NT; nt++)
                    mma16816(acc[mt][nt], afr[mt], bfr[nt]);
        }
    }

    const int g = lane >> 2, tg = lane & 3;
#pragma unroll
    for (int mt = 0; mt < 2; mt++) {
        const int row = bm + mw * 32 + mt * 16 + g;
#pragma unroll
        for (int nt = 0; nt < NT; nt++) {
            const int col = bn + nw * WN + nt * 8 + tg * 2;
            if constexpr (sizeof(CT) == 2) {
                *reinterpret_cast<__half2*>((__half*)C + (long)row * ldc + col) =
                    __floats2half2_rn(acc[mt][nt][0], acc[mt][nt][1]);
                *reinterpret_cast<__half2*>((__half*)C + (long)(row + 8) * ldc + col) =
                    __floats2half2_rn(acc[mt][nt][2], acc[mt][nt][3]);
            } else {
                *reinterpret_cast<float2*>((float*)C + (long)row * ldc + col) =
                    make_float2(acc[mt][nt][0], acc[mt][nt][1]);
                *reinterpret_cast<float2*>((float*)C + (long)(row + 8) * ldc + col) =
                    make_float2(acc[mt][nt][2], acc[mt][nt][3]);
            }
        }
    }
}

// ---------------- fused flash attention: scores + softmax + PV ----------------
// Q fragments hoisted into registers (loaded once at j==0).
#define FBLK  128
#define NBLK  (S_/FBLK)   // 16
#define PADQ  200
#define PADV  136

__global__ __launch_bounds__(256, 1)
void flash_kernel(const __half* __restrict__ q, const __half* __restrict__ keff,
                  const __half* __restrict__ veff, __half* __restrict__ attn)
{
    extern __shared__ char smem[];
    const uint32_t sQa = su32(smem);
    const uint32_t sKa[2] = { sQa + 128*PADQ*2, sQa + 2*128*PADQ*2 };
    const uint32_t sVa[2] = { sQa + 3*128*PADQ*2, sQa + 3*128*PADQ*2 + 128*PADV*2 };

    const int z = blockIdx.z;                  // bh
    const int b = z >> 4, h = z & (NH_-1);
    const int iblk = (NBLK - 1) - blockIdx.x;  // heavy blocks first

    const int tid = threadIdx.x, lane = tid & 31, w = tid >> 5;
    const int g = lane >> 2, tg = lane & 3;
    const int m0r = w * 16;

    const __half* Qbase = q + (long)(b*S_ + iblk*FBLK) * (NH_*QHD_) + h*QHD_;
    const __half* Kbase = keff + (long)z * S_ * QHD_;
    const __half* Vbase = veff + (long)z * VDIM_ * S_;

    for (int v = tid; v < 128*24; v += 256) {
        int r = v / 24, c = v % 24;
        CP_ASYNC16(sQa + (r*PADQ + c*8)*2, Qbase + (long)r*(NH_*QHD_) + c*8);
    }
    auto loadK = [&](int j, int s){
        const __half* kb = Kbase + (long)j*FBLK*QHD_;
        for (int v = tid; v < 128*24; v += 256) {
            int r = v / 24, c = v % 24;
            CP_ASYNC16(sKa[s] + (r*PADQ + c*8)*2, kb + (long)r*QHD_ + c*8);
        }
    };
    auto loadV = [&](int j, int s){
        const __half* vb = Vbase + j*FBLK;
        for (int v = tid; v < 128*16; v += 256) {
            int r = v >> 4, c = v & 15;
            CP_ASYNC16(sVa[s] + (r*PADV + c*8)*2, vb + (long)r*S_ + c*8);
        }
    };
    loadK(0, 0); loadV(0, 0); CP_COMMIT();

    float Oacc[16][4];
#pragma unroll
    for (int nt = 0; nt < 16; nt++)
#pragma unroll
        for (int i = 0; i < 4; i++) Oacc[nt][i] = 0.f;
    float m0 = -1e30f, m1 = -1e30f, l0 = 0.f, l1 = 0.f;
    const float scale = 0.07216878364870322f;   // 192^-0.5

    const int arow = lane & 15;
    const int acol = (lane >> 4) * 8;
    const int brow = (lane & 7) + ((lane >> 4) << 3);
    const int bcol = ((lane >> 3) & 1) * 8;

    uint32_t qfr[QHD_/16][4];                  // 12 k-slices x 4 regs, loaded at j==0

    for (int j = 0; j <= iblk; j++) {
        const int s = j & 1;
        CP_WAIT(0);
        __syncthreads();
        if (j == 0) {
#pragma unroll
            for (int kk16 = 0; kk16 < QHD_/16; kk16++)
                ldmx4(qfr[kk16][0], qfr[kk16][1], qfr[kk16][2], qfr[kk16][3],
                      sQa + (uint32_t)(((m0r + arow)*PADQ + kk16*16 + acol)*2));
        }
        if (j < iblk) { loadK(j+1, s^1); loadV(j+1, s^1); CP_COMMIT(); }

        // ---- S = Q @ Keff_j^T ----
        float Sacc[16][4];
#pragma unroll
        for (int nt = 0; nt < 16; nt++)
#pragma unroll
            for (int i = 0; i < 4; i++) Sacc[nt][i] = 0.f;

#pragma unroll
        for (int kk16 = 0; kk16 < QHD_/16; kk16++) {
            uint32_t bfr[16][2];
#pragma unroll
            for (int p = 0; p < 8; p++)
                ldmx4(bfr[2*p][0], bfr[2*p][1], bfr[2*p+1][0], bfr[2*p+1][1],
                      sKa[s] + (uint32_t)(((p*16 + brow)*PADQ + kk16*16 + bcol)*2));
#pragma unroll
            for (int nt = 0; nt < 16; nt++)
                mma16816(Sacc[nt], qfr[kk16], bfr[nt]);
        }

        // ---- causal mask on diagonal block ----
        if (j == iblk) {
            const int r0 = m0r + g, r1 = r0 + 8;
#pragma unroll
            for (int nt = 0; nt < 16; nt++) {
                const int c0 = nt*8 + tg*2;
                if (c0     > r0) Sacc[nt][0] = -1e30f;
                if (c0 + 1 > r0) Sacc[nt][1] = -1e30f;
                if (c0     > r1) Sacc[nt][2] = -1e30f;
                if (c0 + 1 > r1) Sacc[nt][3] = -1e30f;
            }
        }

        // ---- online softmax ----
        float bm0 = -1e30f, bm1 = -1e30f;
#pragma unroll
        for (int nt = 0; nt < 16; nt++) {
            bm0 = fmaxf(bm0, fmaxf(Sacc[nt][0], Sacc[nt][1]));
            bm1 = fmaxf(bm1, fmaxf(Sacc[nt][2], Sacc[nt][3]));
        }
        bm0 = fmaxf(bm0, __shfl_xor_sync(0xffffffffu, bm0, 1));
        bm0 = fmaxf(bm0, __shfl_xor_sync(0xffffffffu, bm0, 2));
        bm1 = fmaxf(bm1, __shfl_xor_sync(0xffffffffu, bm1, 1));
        bm1 = fmaxf(bm1, __shfl_xor_sync(0xffffffffu, bm1, 2));
        const float mn0 = fmaxf(m0, bm0), mn1 = fmaxf(m1, bm1);
        const float corr0 = __expf((m0 - mn0) * scale);
        const float corr1 = __expf((m1 - mn1) * scale);
        m0 = mn0; m1 = mn1;
        l0 *= corr0; l1 *= corr1;
#pragma unroll
        for (int nt = 0; nt < 16; nt++) {
            Oacc[nt][0] *= corr0; Oacc[nt][1] *= corr0;
            Oacc[nt][2] *= corr1; Oacc[nt][3] *= corr1;
        }

        // ---- P = exp((S-m)*scale); O += P @ Veff_j ----
#pragma unroll
        for (int t = 0; t < 8; t++) {
            const float e00 = __expf((Sacc[2*t  ][0] - m0) * scale);
            const float e01 = __expf((Sacc[2*t  ][1] - m0) * scale);
            const float e02 = __expf((Sacc[2*t  ][2] - m1) * scale);
            const float e03 = __expf((Sacc[2*t  ][3] - m1) * scale);
            const float e10 = __expf((Sacc[2*t+1][0] - m0) * scale);
            const float e11 = __expf((Sacc[2*t+1][1] - m0) * scale);
            const float e12 = __expf((Sacc[2*t+1][2] - m1) * scale);
            const float e13 = __expf((Sacc[2*t+1][3] - m1) * scale);
            l0 += e00 + e01 + e10 + e11;
            l1 += e02 + e03 + e12 + e13;
            uint32_t pa[4];
            pa[0] = packh2(e00, e01);
            pa[1] = packh2(e02, e03);
            pa[2] = packh2(e10, e11);
            pa[3] = packh2(e12, e13);
            uint32_t bfr[16][2];
#pragma unroll
            for (int p = 0; p < 8; p++)
                ldmx4(bfr[2*p][0], bfr[2*p][1], bfr[2*p+1][0], bfr[2*p+1][1],
                      sVa[s] + (uint32_t)(((p*16 + brow)*PADV + t*16 + bcol)*2));
#pragma unroll
            for (int nt = 0; nt < 16; nt++)
                mma16816(Oacc[nt], pa, bfr[nt]);
        }
    }

    // ---- finalize ----
    l0 += __shfl_xor_sync(0xffffffffu, l0, 1);
    l0 += __shfl_xor_sync(0xffffffffu, l0, 2);
    l1 += __shfl_xor_sync(0xffffffffu, l1, 1);
    l1 += __shfl_xor_sync(0xffffffffu, l1, 2);
    const float inv0 = 1.0f / l0, inv1 = 1.0f / l1;

    const long s0 = (long)(b*S_ + iblk*FBLK + m0r + g);
    __half* o0 = attn + (s0 * NH_ + h) * VDIM_;
    __half* o1 = attn + ((s0 + 8) * NH_ + h) * VDIM_;
#pragma unroll
    for (int nt = 0; nt < 16; nt++) {
        const int col = nt*8 + tg*2;
        *reinterpret_cast<__half2*>(o0 + col) = __floats2half2_rn(Oacc[nt][0]*inv0, Oacc[nt][1]*inv0);
        *reinterpret_cast<__half2*>(o1 + col) = __floats2half2_rn(Oacc[nt][2]*inv1, Oacc[nt][3]*inv1);
    }
}

// ---------------- converts ----------------
__global__ __launch_bounds__(256) void f32tof16(const float* __restrict__ in, __half* __restrict__ out, long n4)
{
    long i = blockIdx.x * 256L + threadIdx.x;
    long stride = (long)gridDim.x * 256;
    for (; i < n4; i += stride) {
        float4 v = reinterpret_cast<const float4*>(in)[i];
        reinterpret_cast<__half2*>(out)[2*i]   = __floats2half2_rn(v.x, v.y);
        reinterpret_cast<__half2*>(out)[2*i+1] = __floats2half2_rn(v.z, v.w);
    }
}

__global__ __launch_bounds__(256) void transp_f32f16(const float* __restrict__ in, __half* __restrict__ out,
                                                     int ldin, int ldout, long inB, long outB)
{
    __shared__ float t[32][33];
    const int z = blockIdx.z;
    in += (long)z * inB; out += (long)z * outB;
    const int r0 = blockIdx.y * 32, c0 = blockIdx.x * 32;
    const int x = threadIdx.x & 31, y = threadIdx.x >> 5;
#pragma unroll
    for (int i = 0; i < 32; i += 8)
        t[y + i][x] = in[(long)(r0 + y + i) * ldin + c0 + x];
    __syncthreads();
#pragma unroll
    for (int i = 0; i < 32; i += 8)
        out[(long)(c0 + y + i) * ldout + r0 + x] = __float2half_rn(t[x][y + i]);
}

// ---------------- rms-norm + k_pe rope (ckv side only) ----------------
__global__ __launch_bounds__(128)
void rmsC_kernel(const __half* __restrict__ ckvraw,
                 const int* __restrict__ pos_ids, const float* __restrict__ cosc,
                 const float* __restrict__ sinc, const float* __restrict__ lnw,
                 __half* __restrict__ ckv16, __half* __restrict__ keff)
{
    const int t = blockIdx.x;
    const int b = t / S_, s = t - b * S_;
    const __half* cv = ckvraw + (long)t * DATT_;

    __shared__ float red[4];
    __shared__ __half kpe[64];
    float ss = 0.f;
    for (int i = threadIdx.x; i < RANK_; i += 128) { float v = __half2float(cv[i]); ss += v * v; }
#pragma unroll
    for (int o = 16; o; o >>= 1) ss += __shfl_xor_sync(0xffffffffu, ss, o);
    if ((threadIdx.x & 31) == 0) red[threadIdx.x >> 5] = ss;
    __syncthreads();
    const float inv = rsqrtf((red[0] + red[1] + red[2] + red[3]) * (1.0f / RANK_) + 1e-6f);

    __half* kd = ckv16 + (long)t * RANK_;
    for (int i = threadIdx.x; i < RANK_; i += 128)
        kd[i] = __float2half_rn(__half2float(cv[i]) * inv * lnw[i]);

    const int pos = pos_ids[t];
    const float* cr = cosc + (long)pos * ROPE_;
    const float* sr = sinc + (long)pos * ROPE_;

    if (threadIdx.x < 32) {
        const int j = threadIdx.x;
        const float c = cr[j], sn = sr[j];
        const float e = __half2float(cv[RANK_ + 2*j]), o = __half2float(cv[RANK_ + 2*j + 1]);
        kpe[j]      = __float2half_rn(e * c - o * sn);
        kpe[32 + j] = __float2half_rn(o * c + e * sn);
    }
    __syncthreads();
    {
        const int h = threadIdx.x >> 3, c4 = threadIdx.x & 7;
        __half* kb = keff + ((long)(b * NH_ + h) * S_ + s) * QHD_ + NOPE_;
        reinterpret_cast<uint4*>(kb)[c4] = reinterpret_cast<const uint4*>(kpe)[c4];
    }
}

// ---------------- q_pe rope in place ----------------
__global__ __launch_bounds__(128)
void qpe_kernel(__half* __restrict__ q16, const int* __restrict__ pos_ids,
                const float* __restrict__ cosc, const float* __restrict__ sinc)
{
    const int t = blockIdx.x;
    const int pos = pos_ids[t];
    const float* cr = cosc + (long)pos * ROPE_;
    const float* sr = sinc + (long)pos * ROPE_;

    for (int p = threadIdx.x; p < NH_ * 32; p += 128) {
        const int h = p >> 5, j = p & 31;
        const float c = cr[j], sn = sr[j];
        __half* qs = q16 + (long)t * (NH_*QHD_) + h * QHD_ + NOPE_;
        const float e = __half2float(qs[2*j]), o = __half2float(qs[2*j + 1]);
        __syncwarp();
        qs[j]      = __float2half_rn(e * c - o * sn);
        qs[32 + j] = __float2half_rn(o * c + e * sn);
    }
}

// ---------------- host ----------------
template<typename CT>
static void hgemm_t(const __half* A, const __half* B, CT* C,
                    int M, int N, int K, int lda, int ldb, int ldc, int Z, int zdiv,
                    long aO, long aI, long bO, long bI, long cO, long cI,
                    cudaStream_t st)
{
    if (N % 128 == 0) {
        int sm = 3 * (128 + 128) * PAD_ * 2;
        cudaFuncSetAttribute(hgemm_mma<128, CT>, cudaFuncAttributeMaxDynamicSharedMemorySize, sm);
        dim3 g(N / 128, M / 128, Z);
        hgemm_mma<128, CT><<<g, 256, sm, st>>>(A, B, C, K, lda, ldb, ldc, zdiv, aO, aI, bO, bI, cO, cI);
    } else {
        int sm = 3 * (128 + 64) * PAD_ * 2;
        cudaFuncSetAttribute(hgemm_mma<64, CT>, cudaFuncAttributeMaxDynamicSharedMemorySize, sm);
        dim3 g(N / 64, M / 128, Z);
        hgemm_mma<64, CT><<<g, 256, sm, st>>>(A, B, C, K, lda, ldb, ldc, zdiv, aO, aI, bO, bI, cO, cI);
    }
}

static void cvt(const float* in, __half* out, long n, cudaStream_t st)
{
    long n4 = n / 4;
    int blocks = (int)((n4 + 255) / 256); if (blocks > 8192) blocks = 8192;
    f32tof16<<<blocks, 256, 0, st>>>(in, out, n4);
}

extern "C" void kernel_launch(void* const* d_in, const int* in_sizes, int n_in,
                              void* d_out, int out_size)
{
    const float* hs    = (const float*)d_in[0];
    const int*   pos   = (const int*)d_in[2];
    const float* cosc  = (const float*)d_in[3];
    const float* sinc  = (const float*)d_in[4];
    const float* Wq    = (const float*)d_in[5];
    const float* Wkv_a = (const float*)d_in[6];
    const float* lnw   = (const float*)d_in[7];
    const float* Wkv_b = (const float*)d_in[8];
    const float* Wo    = (const float*)d_in[9];
    float* out = (float*)d_out;

    __half *hs16, *WqT, *WkvaT, *WoT, *Wkvb16, *q16, *ckvraw16, *ckv16, *keff16, *veffT, *attn16;
    cudaGetSymbolAddress((void**)&hs16, g_hs16);
    cudaGetSymbolAddress((void**)&WqT, g_WqT16);
    cudaGetSymbolAddress((void**)&WkvaT, g_WkvaT16);
    cudaGetSymbolAddress((void**)&WoT, g_WoT16);
    cudaGetSymbolAddress((void**)&Wkvb16, g_Wkvb16);
    cudaGetSymbolAddress((void**)&q16, g_q16);
    cudaGetSymbolAddress((void**)&ckvraw16, g_ckvraw16);
    cudaGetSymbolAddress((void**)&ckv16, g_ckv16);
    cudaGetSymbolAddress((void**)&keff16, g_keff16);
    cudaGetSymbolAddress((void**)&veffT, g_veffT16);
    cudaGetSymbolAddress((void**)&attn16, g_attn16);

    // Legal fork: s2's first op waits on evA recorded in the capturing stream.
    cudaStream_t s2;
    cudaStreamCreateWithFlags(&s2, cudaStreamNonBlocking);
    cudaEvent_t evA, evB, evD;
    cudaEventCreateWithFlags(&evA, cudaEventDisableTiming);
    cudaEventCreateWithFlags(&evB, cudaEventDisableTiming);
    cudaEventCreateWithFlags(&evD, cudaEventDisableTiming);
    cudaStream_t s0 = 0;

    // ---- s0: hs convert, then fork ----
    cvt(hs, hs16, (long)NTOK_ * H_, s0);
    cudaEventRecord(evA, s0);
    cudaStreamWaitEvent(s2, evA, 0);

    // ---- s2: kv-side prep + ckvproj + rmsC + veff (all q-independent) ----
    transp_f32f16<<<dim3(DATT_/32, H_/32, 1), 256, 0, s2>>>(Wkv_a, WkvaT, DATT_, H_, 0, 0);
    transp_f32f16<<<dim3(H_/32, H_/32, 1), 256, 0, s2>>>(Wo, WoT, H_, H_, 0, 0);
    cvt(Wkv_b, Wkvb16, (long)NH_ * 256 * RANK_, s2);
    hgemm_t<__half>(hs16, WkvaT, ckvraw16, NTOK_, DATT_, H_, H_, H_, DATT_, 1, 1,
                    0,0,0,0,0,0, s2);
    rmsC_kernel<<<NTOK_, 128, 0, s2>>>(ckvraw16, pos, cosc, sinc, lnw, ckv16, keff16);
    cudaEventRecord(evB, s2);
    hgemm_t<__half>(Wkvb16 + (long)NOPE_*RANK_, ckv16, veffT, VDIM_, S_, RANK_,
          RANK_, RANK_, S_,
          B_*NH_, NH_,
          0, (long)256*RANK_,
          (long)S_*RANK_, 0,
          (long)NH_*VDIM_*S_, (long)VDIM_*S_, s2);
    cudaEventRecord(evD, s2);

    // ---- s0: WqT + q projection + q_pe rope ----
    transp_f32f16<<<dim3((NH_*QHD_)/32, H_/32, 1), 256, 0, s0>>>(Wq, WqT, NH_*QHD_, H_, 0, 0);
    hgemm_t<__half>(hs16, WqT, q16, NTOK_, NH_*QHD_, H_, H_, H_, NH_*QHD_, 1, 1,
                    0,0,0,0,0,0, s0);
    qpe_kernel<<<NTOK_, 128, 0, s0>>>(q16, pos, cosc, sinc);

    // ---- s0: keff (needs ckv16 from s2) ----
    cudaStreamWaitEvent(s0, evB, 0);
    hgemm_t<__half>(ckv16, Wkvb16, keff16, S_, NOPE_, RANK_, RANK_, RANK_, QHD_,
          B_*NH_, NH_,
          (long)S_*RANK_, 0,
          0, (long)256*RANK_,
          (long)NH_*S_*QHD_, (long)S_*QHD_, s0);

    // ---- join: flash needs veff from s2 ----
    cudaStreamWaitEvent(s0, evD, 0);
    {
        int sm = (3*128*PADQ + 2*128*PADV) * 2;   // 223232 bytes
        cudaFuncSetAttribute(flash_kernel, cudaFuncAttributeMaxDynamicSharedMemorySize, sm);
        dim3 g(NBLK, 1, B_*NH_);
        flash_kernel<<<g, 256, sm, s0>>>(q16, keff16, veffT, attn16);
    }

    // ---- final projection ----
    hgemm_t<float>(attn16, WoT, out, NTOK_, H_, NH_*VDIM_, NH_*VDIM_, NH_*VDIM_, H_, 1, 1,
                   0,0,0,0,0,0, s0);
}